// round 6
// baseline (speedup 1.0000x reference)
#include <cuda_runtime.h>
#include <cuda_fp16.h>

// Problem shape (fixed per dataset)
#define NN   50000
#define EE_CAP 1650512   // E + N self loops, with margin
#define D    128
#define DOUT 64
#define SCAN_B 256

// ---- device scratch (no allocation allowed) ----
__device__ __half g_hh[NN * D];     // fp16 transformed features for the edge gather
__device__ float  g_x[NN * D];      // aggregation output / next layer input
__device__ float  g_ssrc[NN];       // h @ att_src
__device__ float  g_sdst[NN];       // h @ att_dst
__device__ int    g_deg[NN];
__device__ int    g_offs[NN + 1];
__device__ int    g_cursor[NN];
__device__ int    g_bsum[(NN + SCAN_B - 1) / SCAN_B];
__device__ int    g_boff[(NN + SCAN_B - 1) / SCAN_B];
__device__ int    g_esrc[EE_CAP];   // CSR-by-dst: source node per edge

// packed f32x2 fma helpers
__device__ __forceinline__ void ffma2(unsigned long long& acc,
                                      unsigned long long a,
                                      unsigned long long b) {
    asm("fma.rn.f32x2 %0, %1, %2, %0;" : "+l"(acc) : "l"(a), "l"(b));
}
__device__ __forceinline__ unsigned long long dup2(float v) {
    unsigned long long r;
    asm("mov.b64 %0, {%1, %1};" : "=l"(r) : "f"(v));
    return r;
}

// ---------------------------------------------------------------- CSR build
__global__ void hist_kernel(const int* __restrict__ ei, int E, int n) {
    int i0 = (blockIdx.x * blockDim.x + threadIdx.x) * 4;
#pragma unroll
    for (int u = 0; u < 4; u++) {
        int i = i0 + u;
        if (i < E) atomicAdd(&g_deg[ei[E + i]], 1);
        else if (i < E + n) atomicAdd(&g_deg[i - E], 1);
    }
}

__device__ __forceinline__ int block_excl_scan(int v, int tid, int* warp_sums) {
    int lane = tid & 31, wid = tid >> 5;
    int x = v;
#pragma unroll
    for (int o = 1; o < 32; o <<= 1) {
        int y = __shfl_up_sync(0xffffffffu, x, o);
        if (lane >= o) x += y;
    }
    if (lane == 31) warp_sums[wid] = x;
    __syncthreads();
    int base = 0;
#pragma unroll
    for (int w = 0; w < SCAN_B / 32; w++)
        if (w < wid) base += warp_sums[w];
    return base + x - v;   // exclusive
}

__global__ void scan1_kernel(int n) {
    __shared__ int ws[SCAN_B / 32];
    int tid = threadIdx.x;
    int i = blockIdx.x * SCAN_B + tid;
    int v = (i < n) ? g_deg[i] : 0;
    int ex = block_excl_scan(v, tid, ws);
    if (i < n) g_offs[i] = ex;
    if (tid == SCAN_B - 1) g_bsum[blockIdx.x] = ex + v;
}

__global__ void scan2_kernel(int nb) {
    __shared__ int ws[SCAN_B / 32];
    int tid = threadIdx.x;
    int v = (tid < nb) ? g_bsum[tid] : 0;
    int ex = block_excl_scan(v, tid, ws);
    if (tid < nb) g_boff[tid] = ex;
}

__global__ void scan3_kernel(int n, int total) {
    int i = blockIdx.x * SCAN_B + threadIdx.x;
    if (i < n) {
        int o = g_offs[i] + g_boff[blockIdx.x];
        g_offs[i] = o;
        g_cursor[i] = o;
    }
    if (i == 0) g_offs[n] = total;
}

__global__ void scatter_kernel(const int* __restrict__ ei, int E, int n) {
    int i0 = (blockIdx.x * blockDim.x + threadIdx.x) * 4;
#pragma unroll
    for (int u = 0; u < 4; u++) {
        int i = i0 + u;
        if (i < E) {
            int s = ei[i];
            int d = ei[E + i];
            int p = atomicAdd(&g_cursor[d], 1);
            g_esrc[p] = s;
        } else if (i < E + n) {
            int v = i - E;
            int p = atomicAdd(&g_cursor[v], 1);
            g_esrc[p] = v;
        }
    }
}

// ---------------------------------------------------------------- GEMM (+ fused attention dots)
// FFMA2 inner product. If Y != nullptr, writes fp32 output; if Yh != nullptr,
// writes fp16 output; if asrc != nullptr (COLS==128), computes per-row
// attention dot products via warp shfl-reduce (warp = one row-group holding
// all 128 columns of 8 rows).
template <int COLS>
__global__ void gemm_kernel(const float* __restrict__ X, const float* __restrict__ W,
                            const float* __restrict__ bias, float* __restrict__ Y,
                            __half* __restrict__ Yh,
                            const float* __restrict__ asrc,
                            const float* __restrict__ adst, int n) {
    extern __shared__ float sm[];
    float* Ws = sm;              // D * COLS
    float* Xs = sm + D * COLS;   // 32 * D
    const int CG = COLS / 4;
    int tid = threadIdx.x;
    int cg = tid % CG;
    int rg = tid / CG;           // 0..3
    int rowbase = blockIdx.x * 32;

    for (int i = tid; i < D * COLS; i += COLS) Ws[i] = W[i];
    for (int i = tid; i < 32 * D; i += COLS) {
        int r = rowbase + (i >> 7);
        Xs[i] = (r < n) ? X[(size_t)r * D + (i & 127)] : 0.f;
    }
    __syncthreads();

    unsigned long long accL[8], accH[8];
#pragma unroll
    for (int r = 0; r < 8; r++) { accL[r] = 0ull; accH[r] = 0ull; }

#pragma unroll 4
    for (int k = 0; k < D; k++) {
        ulonglong2 w2 = *(const ulonglong2*)&Ws[k * COLS + cg * 4];
#pragma unroll
        for (int rr = 0; rr < 8; rr++) {
            unsigned long long xx = dup2(Xs[(rg * 8 + rr) * D + k]);
            ffma2(accL[rr], xx, w2.x);
            ffma2(accH[rr], xx, w2.y);
        }
    }

    float4 b4 = make_float4(0.f, 0.f, 0.f, 0.f);
    if (bias) b4 = *(const float4*)&bias[cg * 4];

    float4 av = make_float4(0.f, 0.f, 0.f, 0.f);
    float4 dv = make_float4(0.f, 0.f, 0.f, 0.f);
    if (asrc) {
        av = *(const float4*)&asrc[cg * 4];
        dv = *(const float4*)&adst[cg * 4];
    }

#pragma unroll
    for (int rr = 0; rr < 8; rr++) {
        int r = rowbase + rg * 8 + rr;
        if (r < n) {
            float2 lo = *(float2*)&accL[rr];
            float2 hi = *(float2*)&accH[rr];
            float4 o;
            o.x = lo.x + b4.x;
            o.y = lo.y + b4.y;
            o.z = hi.x + b4.z;
            o.w = hi.y + b4.w;
            if (Y) *(float4*)&Y[(size_t)r * COLS + cg * 4] = o;
            if (Yh) {
                __half2 h0 = __floats2half2_rn(o.x, o.y);
                __half2 h1 = __floats2half2_rn(o.z, o.w);
                uint2 pk;
                pk.x = *(unsigned*)&h0;
                pk.y = *(unsigned*)&h1;
                *(uint2*)&Yh[(size_t)r * COLS + cg * 4] = pk;
            }
            if (asrc && COLS == 128) {
                float p = o.x * av.x + o.y * av.y + o.z * av.z + o.w * av.w;
                float q = o.x * dv.x + o.y * dv.y + o.z * dv.z + o.w * dv.w;
#pragma unroll
                for (int of = 16; of; of >>= 1) {
                    p += __shfl_xor_sync(0xffffffffu, p, of);
                    q += __shfl_xor_sync(0xffffffffu, q, of);
                }
                if (cg == 0) {
                    g_ssrc[r] = p;
                    g_sdst[r] = q;
                }
            }
        }
    }
}

// ---------------------------------------------------------------- fused alpha + aggregation
// One warp per destination node. Per 64-edge chunk: lanes compute
// exp(relu(e)) (NEG_SLOPE=0 => e>=0, max-shift unnecessary) and stage
// {src, ex} in per-warp SMEM; then the warp consumes the chunk, gathering
// fp16 rows with 4-wide MLP and FFMA2 accumulation. Normalize once at end.
#define CH 64
__global__ void __launch_bounds__(256) gat_edge_kernel(
    const __half* __restrict__ hh, const float* __restrict__ bias,
    float* __restrict__ out, int n, int do_relu) {
    __shared__ float2 stage[8][CH];
    int gt = blockIdx.x * blockDim.x + threadIdx.x;
    int node = gt >> 5, lane = gt & 31;
    int wslot = (threadIdx.x >> 5);
    if (node >= n) return;

    int beg = g_offs[node];
    int end = g_offs[node + 1];
    float sd = g_sdst[node];

    float denom = 0.f;
    unsigned long long acc0 = 0ull, acc1 = 0ull;

    for (int cb = beg; cb < end; cb += CH) {
        int m = min(CH, end - cb);
        for (int t = lane; t < m; t += 32) {
            int s = g_esrc[cb + t];
            float ex = __expf(fmaxf(g_ssrc[s] + sd, 0.f));
            denom += ex;
            stage[wslot][t] = make_float2(__int_as_float(s), ex);
        }
        __syncwarp();

        int k = 0;
        for (; k + 4 <= m; k += 4) {
            float2 p0 = stage[wslot][k + 0];
            float2 p1 = stage[wslot][k + 1];
            float2 p2 = stage[wslot][k + 2];
            float2 p3 = stage[wslot][k + 3];
            uint2 v0 = *(const uint2*)&hh[(size_t)__float_as_int(p0.x) * D + lane * 4];
            uint2 v1 = *(const uint2*)&hh[(size_t)__float_as_int(p1.x) * D + lane * 4];
            uint2 v2 = *(const uint2*)&hh[(size_t)__float_as_int(p2.x) * D + lane * 4];
            uint2 v3 = *(const uint2*)&hh[(size_t)__float_as_int(p3.x) * D + lane * 4];
            float2 a0 = __half22float2(*(__half2*)&v0.x);
            float2 b0 = __half22float2(*(__half2*)&v0.y);
            float2 a1 = __half22float2(*(__half2*)&v1.x);
            float2 b1 = __half22float2(*(__half2*)&v1.y);
            float2 a2 = __half22float2(*(__half2*)&v2.x);
            float2 b2 = __half22float2(*(__half2*)&v2.y);
            float2 a3 = __half22float2(*(__half2*)&v3.x);
            float2 b3 = __half22float2(*(__half2*)&v3.y);
            unsigned long long w0 = dup2(p0.y), w1 = dup2(p1.y);
            unsigned long long w2 = dup2(p2.y), w3 = dup2(p3.y);
            ffma2(acc0, w0, *(unsigned long long*)&a0);
            ffma2(acc1, w0, *(unsigned long long*)&b0);
            ffma2(acc0, w1, *(unsigned long long*)&a1);
            ffma2(acc1, w1, *(unsigned long long*)&b1);
            ffma2(acc0, w2, *(unsigned long long*)&a2);
            ffma2(acc1, w2, *(unsigned long long*)&b2);
            ffma2(acc0, w3, *(unsigned long long*)&a3);
            ffma2(acc1, w3, *(unsigned long long*)&b3);
        }
        for (; k < m; k++) {
            float2 pk = stage[wslot][k];
            uint2 v = *(const uint2*)&hh[(size_t)__float_as_int(pk.x) * D + lane * 4];
            float2 a = __half22float2(*(__half2*)&v.x);
            float2 b = __half22float2(*(__half2*)&v.y);
            unsigned long long w = dup2(pk.y);
            ffma2(acc0, w, *(unsigned long long*)&a);
            ffma2(acc1, w, *(unsigned long long*)&b);
        }
        __syncwarp();
    }

#pragma unroll
    for (int o = 16; o; o >>= 1) denom += __shfl_xor_sync(0xffffffffu, denom, o);
    float inv = 1.f / denom;

    float2 lo = *(float2*)&acc0;
    float2 hi = *(float2*)&acc1;
    float4 b4 = *(const float4*)&bias[lane * 4];
    float4 o4;
    o4.x = lo.x * inv + b4.x;
    o4.y = lo.y * inv + b4.y;
    o4.z = hi.x * inv + b4.z;
    o4.w = hi.y * inv + b4.w;
    if (do_relu) {
        o4.x = fmaxf(o4.x, 0.f);
        o4.y = fmaxf(o4.y, 0.f);
        o4.z = fmaxf(o4.z, 0.f);
        o4.w = fmaxf(o4.w, 0.f);
    }
    *(float4*)&out[(size_t)node * D + lane * 4] = o4;
}

// ---------------------------------------------------------------- launch
extern "C" void kernel_launch(void* const* d_in, const int* in_sizes, int n_in,
                              void* d_out, int out_size) {
    const float* node_x = (const float*)d_in[0];
    const int*   ei     = (const int*)d_in[1];
    const float* W1     = (const float*)d_in[2];
    const float* as1    = (const float*)d_in[3];
    const float* ad1    = (const float*)d_in[4];
    const float* b1     = (const float*)d_in[5];
    const float* W2     = (const float*)d_in[6];
    const float* as2    = (const float*)d_in[7];
    const float* ad2    = (const float*)d_in[8];
    const float* b2     = (const float*)d_in[9];
    const float* Wout   = (const float*)d_in[10];
    const float* bout   = (const float*)d_in[11];
    float* out = (float*)d_out;

    int n = in_sizes[0] / D;       // 50000
    int E = in_sizes[1] / 2;       // 1600000

    float* x_ptr;
    __half* hh_ptr;
    int* deg_ptr;
    cudaGetSymbolAddress((void**)&x_ptr, g_x);
    cudaGetSymbolAddress((void**)&hh_ptr, g_hh);
    cudaGetSymbolAddress((void**)&deg_ptr, g_deg);

    const int SMEM128 = (D * 128 + 32 * D) * (int)sizeof(float);   // 80 KB
    const int SMEM64  = (D * 64 + 32 * D) * (int)sizeof(float);    // 48 KB

    // one-time init (first call = uncaptured correctness run)
    static bool inited = false;
    static cudaStream_t s2;
    static cudaEvent_t evF, evJ;
    if (!inited) {
        cudaFuncSetAttribute(gemm_kernel<128>, cudaFuncAttributeMaxDynamicSharedMemorySize, SMEM128);
        cudaFuncSetAttribute(gemm_kernel<64>, cudaFuncAttributeMaxDynamicSharedMemorySize, SMEM64);
        cudaStreamCreateWithFlags(&s2, cudaStreamNonBlocking);
        cudaEventCreateWithFlags(&evF, cudaEventDisableTiming);
        cudaEventCreateWithFlags(&evJ, cudaEventDisableTiming);
        inited = true;
    }

    int tot = E + n;
    int nb = (n + SCAN_B - 1) / SCAN_B;
    int agg_grid = (n * 32 + 255) / 256;
    int gemm_grid = (n + 31) / 32;

    // fork: CSR build on s2 concurrent with layer-1 GEMM on stream 0
    cudaEventRecord(evF, 0);
    cudaStreamWaitEvent(s2, evF, 0);

    cudaMemsetAsync(deg_ptr, 0, (size_t)n * sizeof(int), s2);
    hist_kernel<<<(tot + 1023) / 1024, 256, 0, s2>>>(ei, E, n);
    scan1_kernel<<<nb, SCAN_B, 0, s2>>>(n);
    scan2_kernel<<<1, SCAN_B, 0, s2>>>(nb);
    scan3_kernel<<<nb, SCAN_B, 0, s2>>>(n, tot);
    scatter_kernel<<<(tot + 1023) / 1024, 256, 0, s2>>>(ei, E, n);

    // layer-1 GEMM + fused dots (fp16 output only)
    gemm_kernel<128><<<gemm_grid, 128, SMEM128>>>(node_x, W1, nullptr, nullptr, hh_ptr, as1, ad1, n);

    // join
    cudaEventRecord(evJ, s2);
    cudaStreamWaitEvent(0, evJ, 0);

    // layer 1 aggregation
    gat_edge_kernel<<<agg_grid, 256>>>(hh_ptr, b1, x_ptr, n, 1);

    // layer 2
    gemm_kernel<128><<<gemm_grid, 128, SMEM128>>>(x_ptr, W2, nullptr, nullptr, hh_ptr, as2, ad2, n);
    gat_edge_kernel<<<agg_grid, 256>>>(hh_ptr, b2, x_ptr, n, 0);

    // output linear
    gemm_kernel<64><<<gemm_grid, 64, SMEM64>>>(x_ptr, Wout, bout, out, nullptr, nullptr, nullptr, n);
}

// round 7
// speedup vs baseline: 1.2926x; 1.2926x over previous
#include <cuda_runtime.h>
#include <cuda_fp16.h>

// Problem shape (fixed per dataset)
#define NN   50000
#define EE_CAP 1650512   // E + N self loops, with margin
#define D    128
#define DOUT 64
#define SCAN_B 256

// ---- device scratch (no allocation allowed) ----
__device__ __half g_hh[NN * D];     // fp16 transformed features for the edge gather
__device__ float  g_x[NN * D];      // aggregation output / next layer input
__device__ float  g_ssrc[NN];       // h @ att_src
__device__ float  g_sdst[NN];       // h @ att_dst
__device__ __half g_w16a[D * D];    // W1 in fp16
__device__ __half g_w16b[D * D];    // W2 in fp16
__device__ int    g_deg[NN];
__device__ int    g_offs[NN + 1];
__device__ int    g_cursor[NN];
__device__ int    g_bsum[(NN + SCAN_B - 1) / SCAN_B];
__device__ int    g_boff[(NN + SCAN_B - 1) / SCAN_B];
__device__ int    g_esrc[EE_CAP];   // CSR-by-dst: source node per edge

// packed f32x2 fma helpers
__device__ __forceinline__ void ffma2(unsigned long long& acc,
                                      unsigned long long a,
                                      unsigned long long b) {
    asm("fma.rn.f32x2 %0, %1, %2, %0;" : "+l"(acc) : "l"(a), "l"(b));
}
__device__ __forceinline__ unsigned long long dup2(float v) {
    unsigned long long r;
    asm("mov.b64 %0, {%1, %1};" : "=l"(r) : "f"(v));
    return r;
}

// ---------------------------------------------------------------- CSR build
__global__ void hist_kernel(const int* __restrict__ ei, int E, int n) {
    int i0 = (blockIdx.x * blockDim.x + threadIdx.x) * 4;
#pragma unroll
    for (int u = 0; u < 4; u++) {
        int i = i0 + u;
        if (i < E) atomicAdd(&g_deg[ei[E + i]], 1);
        else if (i < E + n) atomicAdd(&g_deg[i - E], 1);
    }
}

__device__ __forceinline__ int block_excl_scan(int v, int tid, int* warp_sums) {
    int lane = tid & 31, wid = tid >> 5;
    int x = v;
#pragma unroll
    for (int o = 1; o < 32; o <<= 1) {
        int y = __shfl_up_sync(0xffffffffu, x, o);
        if (lane >= o) x += y;
    }
    if (lane == 31) warp_sums[wid] = x;
    __syncthreads();
    int base = 0;
#pragma unroll
    for (int w = 0; w < SCAN_B / 32; w++)
        if (w < wid) base += warp_sums[w];
    return base + x - v;   // exclusive
}

__global__ void scan1_kernel(int n) {
    __shared__ int ws[SCAN_B / 32];
    int tid = threadIdx.x;
    int i = blockIdx.x * SCAN_B + tid;
    int v = (i < n) ? g_deg[i] : 0;
    int ex = block_excl_scan(v, tid, ws);
    if (i < n) g_offs[i] = ex;
    if (tid == SCAN_B - 1) g_bsum[blockIdx.x] = ex + v;
}

__global__ void scan2_kernel(int nb) {
    __shared__ int ws[SCAN_B / 32];
    int tid = threadIdx.x;
    int v = (tid < nb) ? g_bsum[tid] : 0;
    int ex = block_excl_scan(v, tid, ws);
    if (tid < nb) g_boff[tid] = ex;
}

__global__ void scan3_kernel(int n, int total) {
    int i = blockIdx.x * SCAN_B + threadIdx.x;
    if (i < n) {
        int o = g_offs[i] + g_boff[blockIdx.x];
        g_offs[i] = o;
        g_cursor[i] = o;
    }
    if (i == 0) g_offs[n] = total;
}

__global__ void scatter_kernel(const int* __restrict__ ei, int E, int n) {
    int i0 = (blockIdx.x * blockDim.x + threadIdx.x) * 4;
#pragma unroll
    for (int u = 0; u < 4; u++) {
        int i = i0 + u;
        if (i < E) {
            int s = ei[i];
            int d = ei[E + i];
            int p = atomicAdd(&g_cursor[d], 1);
            g_esrc[p] = s;
        } else if (i < E + n) {
            int v = i - E;
            int p = atomicAdd(&g_cursor[v], 1);
            g_esrc[p] = v;
        }
    }
}

// ---------------------------------------------------------------- W fp16 pre-convert
__global__ void convert_w_kernel(const float* __restrict__ W1f,
                                 const float* __restrict__ W2f) {
    int i = blockIdx.x * blockDim.x + threadIdx.x;
    if (i < D * D) {
        g_w16a[i] = __float2half_rn(W1f[i]);
        g_w16b[i] = __float2half_rn(W2f[i]);
    }
}

// ---------------------------------------------------------------- HMMA GEMM (GAT layers)
// hh_out[n,128] (fp16) = X[n,128] @ W16[128,128], fp32 accumulate via
// mma.sync.m16n8k16. Fused epilogue: per-row attention dots -> g_ssrc/g_sdst.
// Block = 128 threads (4 warps), 64 rows per block, warp = 16 rows.
#define XPAD 136   // halves per row (8-half pad kills ldmatrix bank conflicts)
__global__ void __launch_bounds__(128) hmma_gemm_kernel(
    const float* __restrict__ X, const __half* __restrict__ W16,
    __half* __restrict__ hh_out,
    const float* __restrict__ asrc, const float* __restrict__ adst, int n) {
    extern __shared__ __half smh[];
    __half* Xs = smh;                 // 64 x XPAD
    __half* Ws = smh + 64 * XPAD;     // 128 x XPAD
    int tid = threadIdx.x;
    int lane = tid & 31;
    int warp = tid >> 5;              // 0..3
    int rowbase = blockIdx.x * 64;

    // load W tile (fp16, coalesced)
    for (int i = tid; i < D * D; i += 128)
        Ws[(i >> 7) * XPAD + (i & 127)] = W16[i];
    // load X tile (fp32 -> fp16), zero-pad tail rows
    for (int i = tid; i < 64 * D; i += 128) {
        int r = rowbase + (i >> 7);
        Xs[(i >> 7) * XPAD + (i & 127)] =
            (r < n) ? __float2half_rn(X[(size_t)r * D + (i & 127)]) : __half(0.f);
    }
    __syncthreads();

    unsigned xs_base = (unsigned)__cvta_generic_to_shared(Xs);
    unsigned ws_base = (unsigned)__cvta_generic_to_shared(Ws);
    int warpRow = warp * 16;

    // preload all 8 A fragments (16x16 each) for this warp's 16 rows
    unsigned a[8][4];
#pragma unroll
    for (int ka = 0; ka < 8; ka++) {
        unsigned addr = xs_base +
            ((warpRow + (lane & 15)) * XPAD + ka * 16 + (lane >> 4) * 8) * 2;
        asm volatile("ldmatrix.sync.aligned.m8n8.x4.shared.b16 {%0,%1,%2,%3}, [%4];"
                     : "=r"(a[ka][0]), "=r"(a[ka][1]), "=r"(a[ka][2]), "=r"(a[ka][3])
                     : "r"(addr));
    }

    int g = lane >> 2;          // row group 0..7
    int c2 = (lane & 3) * 2;    // col pair within 8-col tile
    int rowLo = rowbase + warpRow + g;
    int rowHi = rowLo + 8;

    float psL = 0.f, psH = 0.f, qdL = 0.f, qdH = 0.f;

#pragma unroll
    for (int j = 0; j < 16; j++) {
        float d0 = 0.f, d1 = 0.f, d2 = 0.f, d3 = 0.f;
#pragma unroll
        for (int ka = 0; ka < 8; ka++) {
            unsigned b0, b1;
            unsigned baddr = ws_base + ((ka * 16 + (lane & 15)) * XPAD + j * 8) * 2;
            asm volatile("ldmatrix.sync.aligned.m8n8.x2.trans.shared.b16 {%0,%1}, [%2];"
                         : "=r"(b0), "=r"(b1) : "r"(baddr));
            asm volatile(
                "mma.sync.aligned.m16n8k16.row.col.f32.f16.f16.f32 "
                "{%0,%1,%2,%3}, {%4,%5,%6,%7}, {%8,%9}, {%0,%1,%2,%3};"
                : "+f"(d0), "+f"(d1), "+f"(d2), "+f"(d3)
                : "r"(a[ka][0]), "r"(a[ka][1]), "r"(a[ka][2]), "r"(a[ka][3]),
                  "r"(b0), "r"(b1));
        }
        int col = j * 8 + c2;
        // attention dot partials
        float av0 = asrc[col], av1 = asrc[col + 1];
        float dv0 = adst[col], dv1 = adst[col + 1];
        psL += d0 * av0 + d1 * av1;
        psH += d2 * av0 + d3 * av1;
        qdL += d0 * dv0 + d1 * dv1;
        qdH += d2 * dv0 + d3 * dv1;
        // fp16 store
        if (rowLo < n) {
            __half2 hlo = __floats2half2_rn(d0, d1);
            *(__half2*)&hh_out[(size_t)rowLo * D + col] = hlo;
        }
        if (rowHi < n) {
            __half2 hhi = __floats2half2_rn(d2, d3);
            *(__half2*)&hh_out[(size_t)rowHi * D + col] = hhi;
        }
    }

    // reduce dot partials across the 4 threads sharing a row
    psL += __shfl_xor_sync(0xffffffffu, psL, 1);
    psL += __shfl_xor_sync(0xffffffffu, psL, 2);
    psH += __shfl_xor_sync(0xffffffffu, psH, 1);
    psH += __shfl_xor_sync(0xffffffffu, psH, 2);
    qdL += __shfl_xor_sync(0xffffffffu, qdL, 1);
    qdL += __shfl_xor_sync(0xffffffffu, qdL, 2);
    qdH += __shfl_xor_sync(0xffffffffu, qdH, 1);
    qdH += __shfl_xor_sync(0xffffffffu, qdH, 2);
    if ((lane & 3) == 0) {
        if (rowLo < n) { g_ssrc[rowLo] = psL; g_sdst[rowLo] = qdL; }
        if (rowHi < n) { g_ssrc[rowHi] = psH; g_sdst[rowHi] = qdH; }
    }
}

// ---------------------------------------------------------------- scalar GEMM (out linear)
template <int COLS>
__global__ void gemm_kernel(const float* __restrict__ X, const float* __restrict__ W,
                            const float* __restrict__ bias, float* __restrict__ Y, int n) {
    extern __shared__ float sm[];
    float* Ws = sm;              // D * COLS
    float* Xs = sm + D * COLS;   // 32 * D
    const int CG = COLS / 4;
    int tid = threadIdx.x;
    int cg = tid % CG;
    int rg = tid / CG;           // 0..3
    int rowbase = blockIdx.x * 32;

    for (int i = tid; i < D * COLS; i += COLS) Ws[i] = W[i];
    for (int i = tid; i < 32 * D; i += COLS) {
        int r = rowbase + (i >> 7);
        Xs[i] = (r < n) ? X[(size_t)r * D + (i & 127)] : 0.f;
    }
    __syncthreads();

    unsigned long long accL[8], accH[8];
#pragma unroll
    for (int r = 0; r < 8; r++) { accL[r] = 0ull; accH[r] = 0ull; }

#pragma unroll 4
    for (int k = 0; k < D; k++) {
        ulonglong2 w2 = *(const ulonglong2*)&Ws[k * COLS + cg * 4];
#pragma unroll
        for (int rr = 0; rr < 8; rr++) {
            unsigned long long xx = dup2(Xs[(rg * 8 + rr) * D + k]);
            ffma2(accL[rr], xx, w2.x);
            ffma2(accH[rr], xx, w2.y);
        }
    }

    float4 b4 = *(const float4*)&bias[cg * 4];
#pragma unroll
    for (int rr = 0; rr < 8; rr++) {
        int r = rowbase + rg * 8 + rr;
        if (r < n) {
            float2 lo = *(float2*)&accL[rr];
            float2 hi = *(float2*)&accH[rr];
            float4 o;
            o.x = lo.x + b4.x;
            o.y = lo.y + b4.y;
            o.z = hi.x + b4.z;
            o.w = hi.y + b4.w;
            *(float4*)&Y[(size_t)r * COLS + cg * 4] = o;
        }
    }
}

// ---------------------------------------------------------------- fused alpha + aggregation
// One warp per destination node. Per 64-edge chunk: lanes compute exp(relu(e))
// (NEG_SLOPE=0 => e>=0, max-shift unnecessary) and stage {src, ex} in per-warp
// SMEM; then the warp gathers fp16 rows with 4-wide MLP + FFMA2 accumulation.
#define CH 64
__global__ void __launch_bounds__(256) gat_edge_kernel(
    const __half* __restrict__ hh, const float* __restrict__ bias,
    float* __restrict__ out, int n, int do_relu) {
    __shared__ float2 stage[8][CH];
    int gt = blockIdx.x * blockDim.x + threadIdx.x;
    int node = gt >> 5, lane = gt & 31;
    int wslot = (threadIdx.x >> 5);
    if (node >= n) return;

    int beg = g_offs[node];
    int end = g_offs[node + 1];
    float sd = g_sdst[node];

    float denom = 0.f;
    unsigned long long acc0 = 0ull, acc1 = 0ull;

    for (int cb = beg; cb < end; cb += CH) {
        int m = min(CH, end - cb);
        for (int t = lane; t < m; t += 32) {
            int s = g_esrc[cb + t];
            float ex = __expf(fmaxf(g_ssrc[s] + sd, 0.f));
            denom += ex;
            stage[wslot][t] = make_float2(__int_as_float(s), ex);
        }
        __syncwarp();

        int k = 0;
        for (; k + 4 <= m; k += 4) {
            float2 p0 = stage[wslot][k + 0];
            float2 p1 = stage[wslot][k + 1];
            float2 p2 = stage[wslot][k + 2];
            float2 p3 = stage[wslot][k + 3];
            uint2 v0 = *(const uint2*)&hh[(size_t)__float_as_int(p0.x) * D + lane * 4];
            uint2 v1 = *(const uint2*)&hh[(size_t)__float_as_int(p1.x) * D + lane * 4];
            uint2 v2 = *(const uint2*)&hh[(size_t)__float_as_int(p2.x) * D + lane * 4];
            uint2 v3 = *(const uint2*)&hh[(size_t)__float_as_int(p3.x) * D + lane * 4];
            float2 a0 = __half22float2(*(__half2*)&v0.x);
            float2 b0 = __half22float2(*(__half2*)&v0.y);
            float2 a1 = __half22float2(*(__half2*)&v1.x);
            float2 b1 = __half22float2(*(__half2*)&v1.y);
            float2 a2 = __half22float2(*(__half2*)&v2.x);
            float2 b2 = __half22float2(*(__half2*)&v2.y);
            float2 a3 = __half22float2(*(__half2*)&v3.x);
            float2 b3 = __half22float2(*(__half2*)&v3.y);
            unsigned long long w0 = dup2(p0.y), w1 = dup2(p1.y);
            unsigned long long w2 = dup2(p2.y), w3 = dup2(p3.y);
            ffma2(acc0, w0, *(unsigned long long*)&a0);
            ffma2(acc1, w0, *(unsigned long long*)&b0);
            ffma2(acc0, w1, *(unsigned long long*)&a1);
            ffma2(acc1, w1, *(unsigned long long*)&b1);
            ffma2(acc0, w2, *(unsigned long long*)&a2);
            ffma2(acc1, w2, *(unsigned long long*)&b2);
            ffma2(acc0, w3, *(unsigned long long*)&a3);
            ffma2(acc1, w3, *(unsigned long long*)&b3);
        }
        for (; k < m; k++) {
            float2 pk = stage[wslot][k];
            uint2 v = *(const uint2*)&hh[(size_t)__float_as_int(pk.x) * D + lane * 4];
            float2 a = __half22float2(*(__half2*)&v.x);
            float2 b = __half22float2(*(__half2*)&v.y);
            unsigned long long w = dup2(pk.y);
            ffma2(acc0, w, *(unsigned long long*)&a);
            ffma2(acc1, w, *(unsigned long long*)&b);
        }
        __syncwarp();
    }

#pragma unroll
    for (int o = 16; o; o >>= 1) denom += __shfl_xor_sync(0xffffffffu, denom, o);
    float inv = 1.f / denom;

    float2 lo = *(float2*)&acc0;
    float2 hi = *(float2*)&acc1;
    float4 b4 = *(const float4*)&bias[lane * 4];
    float4 o4;
    o4.x = lo.x * inv + b4.x;
    o4.y = lo.y * inv + b4.y;
    o4.z = hi.x * inv + b4.z;
    o4.w = hi.y * inv + b4.w;
    if (do_relu) {
        o4.x = fmaxf(o4.x, 0.f);
        o4.y = fmaxf(o4.y, 0.f);
        o4.z = fmaxf(o4.z, 0.f);
        o4.w = fmaxf(o4.w, 0.f);
    }
    *(float4*)&out[(size_t)node * D + lane * 4] = o4;
}

// ---------------------------------------------------------------- launch
extern "C" void kernel_launch(void* const* d_in, const int* in_sizes, int n_in,
                              void* d_out, int out_size) {
    const float* node_x = (const float*)d_in[0];
    const int*   ei     = (const int*)d_in[1];
    const float* W1     = (const float*)d_in[2];
    const float* as1    = (const float*)d_in[3];
    const float* ad1    = (const float*)d_in[4];
    const float* b1     = (const float*)d_in[5];
    const float* W2     = (const float*)d_in[6];
    const float* as2    = (const float*)d_in[7];
    const float* ad2    = (const float*)d_in[8];
    const float* b2     = (const float*)d_in[9];
    const float* Wout   = (const float*)d_in[10];
    const float* bout   = (const float*)d_in[11];
    float* out = (float*)d_out;

    int n = in_sizes[0] / D;       // 50000
    int E = in_sizes[1] / 2;       // 1600000

    float* x_ptr;
    __half *hh_ptr, *w16a_ptr, *w16b_ptr;
    int* deg_ptr;
    cudaGetSymbolAddress((void**)&x_ptr, g_x);
    cudaGetSymbolAddress((void**)&hh_ptr, g_hh);
    cudaGetSymbolAddress((void**)&w16a_ptr, g_w16a);
    cudaGetSymbolAddress((void**)&w16b_ptr, g_w16b);
    cudaGetSymbolAddress((void**)&deg_ptr, g_deg);

    const int SMEM_HMMA = (64 * XPAD + 128 * XPAD) * (int)sizeof(__half); // ~51 KB
    const int SMEM64 = (D * 64 + 32 * D) * (int)sizeof(float);            // 48 KB
    cudaFuncSetAttribute(hmma_gemm_kernel, cudaFuncAttributeMaxDynamicSharedMemorySize, SMEM_HMMA);
    cudaFuncSetAttribute(gemm_kernel<64>, cudaFuncAttributeMaxDynamicSharedMemorySize, SMEM64);

    int tot = E + n;
    int nb = (n + SCAN_B - 1) / SCAN_B;
    int agg_grid = (n * 32 + 255) / 256;
    int hmma_grid = (n + 63) / 64;
    int gemm_grid = (n + 31) / 32;

    // CSR build + W conversion
    cudaMemsetAsync(deg_ptr, 0, (size_t)n * sizeof(int), 0);
    convert_w_kernel<<<(D * D + 255) / 256, 256>>>(W1, W2);
    hist_kernel<<<(tot + 1023) / 1024, 256>>>(ei, E, n);
    scan1_kernel<<<nb, SCAN_B>>>(n);
    scan2_kernel<<<1, SCAN_B>>>(nb);
    scan3_kernel<<<nb, SCAN_B>>>(n, tot);
    scatter_kernel<<<(tot + 1023) / 1024, 256>>>(ei, E, n);

    // layer 1: HMMA GEMM + fused dots, then fused alpha+aggregate
    hmma_gemm_kernel<<<hmma_grid, 128, SMEM_HMMA>>>(node_x, w16a_ptr, hh_ptr, as1, ad1, n);
    gat_edge_kernel<<<agg_grid, 256>>>(hh_ptr, b1, x_ptr, n, 1);

    // layer 2
    hmma_gemm_kernel<<<hmma_grid, 128, SMEM_HMMA>>>(x_ptr, w16b_ptr, hh_ptr, as2, ad2, n);
    gat_edge_kernel<<<agg_grid, 256>>>(hh_ptr, b2, x_ptr, n, 0);

    // output linear (fp32 scalar)
    gemm_kernel<64><<<gemm_grid, 64, SMEM64>>>(x_ptr, Wout, bout, out, n);
}

// round 8
// speedup vs baseline: 1.3710x; 1.0607x over previous
#include <cuda_runtime.h>
#include <cuda_fp16.h>

// Problem shape (fixed per dataset)
#define NN   50000
#define EE_CAP 1650512   // E + N self loops, with margin
#define D    128
#define DOUT 64
#define SCAN_B 256
#define CONV_BLOCKS 64   // D*D/256 blocks prepended to hist for W conversion

// ---- device scratch (no allocation allowed) ----
__device__ __half g_hh[NN * D];     // fp16 transformed features for the edge gather
__device__ float  g_x[NN * D];      // aggregation output / next layer input
__device__ float  g_ssrc[NN];       // h @ att_src
__device__ float  g_sdst[NN];       // h @ att_dst
__device__ __half g_w16a[D * D];    // W1 in fp16
__device__ __half g_w16b[D * D];    // W2 in fp16
__device__ int    g_deg[NN];
__device__ int    g_offs[NN + 1];
__device__ int    g_cursor[NN];
__device__ int    g_bsum[(NN + SCAN_B - 1) / SCAN_B];
__device__ int    g_esrc[EE_CAP];   // CSR-by-dst: source node per edge

// packed f32x2 fma helpers
__device__ __forceinline__ void ffma2(unsigned long long& acc,
                                      unsigned long long a,
                                      unsigned long long b) {
    asm("fma.rn.f32x2 %0, %1, %2, %0;" : "+l"(acc) : "l"(a), "l"(b));
}
__device__ __forceinline__ unsigned long long dup2(float v) {
    unsigned long long r;
    asm("mov.b64 %0, {%1, %1};" : "=l"(r) : "f"(v));
    return r;
}

// ---------------------------------------------------------------- hist + W convert (merged)
// Blocks [0, CONV_BLOCKS): convert W1/W2 to fp16. Remaining blocks: degree
// histogram, 8 edges per thread for atomic MLP.
__global__ void hist_conv_kernel(const int* __restrict__ ei, int E, int n,
                                 const float* __restrict__ W1f,
                                 const float* __restrict__ W2f) {
    if (blockIdx.x < CONV_BLOCKS) {
        int i = blockIdx.x * 256 + threadIdx.x;
        g_w16a[i] = __float2half_rn(W1f[i]);
        g_w16b[i] = __float2half_rn(W2f[i]);
        return;
    }
    int i0 = (((int)blockIdx.x - CONV_BLOCKS) * 256 + threadIdx.x) * 8;
#pragma unroll
    for (int u = 0; u < 8; u++) {
        int i = i0 + u;
        if (i < E) atomicAdd(&g_deg[ei[E + i]], 1);
        else if (i < E + n) atomicAdd(&g_deg[i - E], 1);
    }
}

// ---------------------------------------------------------------- scan (2 kernels)
__global__ void scan1_kernel(int n) {
    __shared__ int ws[SCAN_B / 32];
    int tid = threadIdx.x;
    int lane = tid & 31, wid = tid >> 5;
    int i = blockIdx.x * SCAN_B + tid;
    int v = (i < n) ? g_deg[i] : 0;
    int x = v;
#pragma unroll
    for (int o = 1; o < 32; o <<= 1) {
        int y = __shfl_up_sync(0xffffffffu, x, o);
        if (lane >= o) x += y;
    }
    if (lane == 31) ws[wid] = x;
    __syncthreads();
    int base = 0;
#pragma unroll
    for (int w = 0; w < SCAN_B / 32; w++)
        if (w < wid) base += ws[w];
    int ex = base + x - v;
    if (i < n) g_offs[i] = ex;
    if (tid == SCAN_B - 1) g_bsum[blockIdx.x] = ex + v;
}

// Each block computes its own prefix over g_bsum (nb <= 256 values), then
// finalizes offsets/cursors. Eliminates the separate middle-scan launch.
__global__ void scan3_kernel(int n, int total) {
    __shared__ int wpart[SCAN_B / 32];
    int tid = threadIdx.x;
    int lane = tid & 31, wid = tid >> 5;
    int part = 0;
    for (int t = tid; t < (int)blockIdx.x; t += SCAN_B) part += g_bsum[t];
#pragma unroll
    for (int o = 16; o; o >>= 1) part += __shfl_xor_sync(0xffffffffu, part, o);
    if (lane == 0) wpart[wid] = part;
    __syncthreads();
    int base = 0;
#pragma unroll
    for (int w = 0; w < SCAN_B / 32; w++) base += wpart[w];

    int i = blockIdx.x * SCAN_B + tid;
    if (i < n) {
        int o = g_offs[i] + base;
        g_offs[i] = o;
        g_cursor[i] = o;
    }
    if (i == 0) g_offs[n] = total;
}

__global__ void scatter_kernel(const int* __restrict__ ei, int E, int n) {
    int i0 = (blockIdx.x * blockDim.x + threadIdx.x) * 8;
#pragma unroll
    for (int u = 0; u < 8; u++) {
        int i = i0 + u;
        if (i < E) {
            int s = ei[i];
            int d = ei[E + i];
            int p = atomicAdd(&g_cursor[d], 1);
            g_esrc[p] = s;
        } else if (i < E + n) {
            int v = i - E;
            int p = atomicAdd(&g_cursor[v], 1);
            g_esrc[p] = v;
        }
    }
}

// ---------------------------------------------------------------- HMMA GEMM (GAT layers)
// hh_out[n,128] (fp16) = X[n,128] @ W16[128,128], fp32 accumulate via
// mma.sync.m16n8k16. Fused epilogue: per-row attention dots -> g_ssrc/g_sdst.
// Block = 128 threads (4 warps), 64 rows per block, warp = 16 rows.
#define XPAD 136   // halves per row (8-half pad kills ldmatrix bank conflicts)
__global__ void __launch_bounds__(128) hmma_gemm_kernel(
    const float* __restrict__ X, const __half* __restrict__ W16,
    __half* __restrict__ hh_out,
    const float* __restrict__ asrc, const float* __restrict__ adst, int n) {
    extern __shared__ __half smh[];
    __half* Xs = smh;                 // 64 x XPAD
    __half* Ws = smh + 64 * XPAD;     // 128 x XPAD
    int tid = threadIdx.x;
    int lane = tid & 31;
    int warp = tid >> 5;              // 0..3
    int rowbase = blockIdx.x * 64;

    for (int i = tid; i < D * D; i += 128)
        Ws[(i >> 7) * XPAD + (i & 127)] = W16[i];
    for (int i = tid; i < 64 * D; i += 128) {
        int r = rowbase + (i >> 7);
        Xs[(i >> 7) * XPAD + (i & 127)] =
            (r < n) ? __float2half_rn(X[(size_t)r * D + (i & 127)]) : __half(0.f);
    }
    __syncthreads();

    unsigned xs_base = (unsigned)__cvta_generic_to_shared(Xs);
    unsigned ws_base = (unsigned)__cvta_generic_to_shared(Ws);
    int warpRow = warp * 16;

    unsigned a[8][4];
#pragma unroll
    for (int ka = 0; ka < 8; ka++) {
        unsigned addr = xs_base +
            ((warpRow + (lane & 15)) * XPAD + ka * 16 + (lane >> 4) * 8) * 2;
        asm volatile("ldmatrix.sync.aligned.m8n8.x4.shared.b16 {%0,%1,%2,%3}, [%4];"
                     : "=r"(a[ka][0]), "=r"(a[ka][1]), "=r"(a[ka][2]), "=r"(a[ka][3])
                     : "r"(addr));
    }

    int g = lane >> 2;
    int c2 = (lane & 3) * 2;
    int rowLo = rowbase + warpRow + g;
    int rowHi = rowLo + 8;

    float psL = 0.f, psH = 0.f, qdL = 0.f, qdH = 0.f;

#pragma unroll
    for (int j = 0; j < 16; j++) {
        float d0 = 0.f, d1 = 0.f, d2 = 0.f, d3 = 0.f;
#pragma unroll
        for (int ka = 0; ka < 8; ka++) {
            unsigned b0, b1;
            unsigned baddr = ws_base + ((ka * 16 + (lane & 15)) * XPAD + j * 8) * 2;
            asm volatile("ldmatrix.sync.aligned.m8n8.x2.trans.shared.b16 {%0,%1}, [%2];"
                         : "=r"(b0), "=r"(b1) : "r"(baddr));
            asm volatile(
                "mma.sync.aligned.m16n8k16.row.col.f32.f16.f16.f32 "
                "{%0,%1,%2,%3}, {%4,%5,%6,%7}, {%8,%9}, {%0,%1,%2,%3};"
                : "+f"(d0), "+f"(d1), "+f"(d2), "+f"(d3)
                : "r"(a[ka][0]), "r"(a[ka][1]), "r"(a[ka][2]), "r"(a[ka][3]),
                  "r"(b0), "r"(b1));
        }
        int col = j * 8 + c2;
        float av0 = asrc[col], av1 = asrc[col + 1];
        float dv0 = adst[col], dv1 = adst[col + 1];
        psL += d0 * av0 + d1 * av1;
        psH += d2 * av0 + d3 * av1;
        qdL += d0 * dv0 + d1 * dv1;
        qdH += d2 * dv0 + d3 * dv1;
        if (rowLo < n) {
            __half2 hlo = __floats2half2_rn(d0, d1);
            *(__half2*)&hh_out[(size_t)rowLo * D + col] = hlo;
        }
        if (rowHi < n) {
            __half2 hhi = __floats2half2_rn(d2, d3);
            *(__half2*)&hh_out[(size_t)rowHi * D + col] = hhi;
        }
    }

    psL += __shfl_xor_sync(0xffffffffu, psL, 1);
    psL += __shfl_xor_sync(0xffffffffu, psL, 2);
    psH += __shfl_xor_sync(0xffffffffu, psH, 1);
    psH += __shfl_xor_sync(0xffffffffu, psH, 2);
    qdL += __shfl_xor_sync(0xffffffffu, qdL, 1);
    qdL += __shfl_xor_sync(0xffffffffu, qdL, 2);
    qdH += __shfl_xor_sync(0xffffffffu, qdH, 1);
    qdH += __shfl_xor_sync(0xffffffffu, qdH, 2);
    if ((lane & 3) == 0) {
        if (rowLo < n) { g_ssrc[rowLo] = psL; g_sdst[rowLo] = qdL; }
        if (rowHi < n) { g_ssrc[rowHi] = psH; g_sdst[rowHi] = qdH; }
    }
}

// ---------------------------------------------------------------- scalar GEMM (out linear)
template <int COLS>
__global__ void gemm_kernel(const float* __restrict__ X, const float* __restrict__ W,
                            const float* __restrict__ bias, float* __restrict__ Y, int n) {
    extern __shared__ float sm[];
    float* Ws = sm;              // D * COLS
    float* Xs = sm + D * COLS;   // 32 * D
    const int CG = COLS / 4;
    int tid = threadIdx.x;
    int cg = tid % CG;
    int rg = tid / CG;
    int rowbase = blockIdx.x * 32;

    for (int i = tid; i < D * COLS; i += COLS) Ws[i] = W[i];
    for (int i = tid; i < 32 * D; i += COLS) {
        int r = rowbase + (i >> 7);
        Xs[i] = (r < n) ? X[(size_t)r * D + (i & 127)] : 0.f;
    }
    __syncthreads();

    unsigned long long accL[8], accH[8];
#pragma unroll
    for (int r = 0; r < 8; r++) { accL[r] = 0ull; accH[r] = 0ull; }

#pragma unroll 4
    for (int k = 0; k < D; k++) {
        ulonglong2 w2 = *(const ulonglong2*)&Ws[k * COLS + cg * 4];
#pragma unroll
        for (int rr = 0; rr < 8; rr++) {
            unsigned long long xx = dup2(Xs[(rg * 8 + rr) * D + k]);
            ffma2(accL[rr], xx, w2.x);
            ffma2(accH[rr], xx, w2.y);
        }
    }

    float4 b4 = *(const float4*)&bias[cg * 4];
#pragma unroll
    for (int rr = 0; rr < 8; rr++) {
        int r = rowbase + rg * 8 + rr;
        if (r < n) {
            float2 lo = *(float2*)&accL[rr];
            float2 hi = *(float2*)&accH[rr];
            float4 o;
            o.x = lo.x + b4.x;
            o.y = lo.y + b4.y;
            o.z = hi.x + b4.z;
            o.w = hi.y + b4.w;
            *(float4*)&Y[(size_t)r * COLS + cg * 4] = o;
        }
    }
}

// ---------------------------------------------------------------- fused alpha + aggregation
// One warp per destination node. Per 64-edge chunk: lanes compute exp(relu(e))
// (NEG_SLOPE=0 => e>=0, max-shift unnecessary) and stage {src, ex} in per-warp
// SMEM; then the warp gathers fp16 rows with 8-wide MLP + FFMA2 accumulation.
#define CH 64
__global__ void __launch_bounds__(256) gat_edge_kernel(
    const __half* __restrict__ hh, const float* __restrict__ bias,
    float* __restrict__ out, int n, int do_relu) {
    __shared__ float2 stage[8][CH];
    int gt = blockIdx.x * blockDim.x + threadIdx.x;
    int node = gt >> 5, lane = gt & 31;
    int wslot = (threadIdx.x >> 5);
    if (node >= n) return;

    int beg = g_offs[node];
    int end = g_offs[node + 1];
    float sd = g_sdst[node];

    float denom = 0.f;
    unsigned long long acc0 = 0ull, acc1 = 0ull;

    for (int cb = beg; cb < end; cb += CH) {
        int m = min(CH, end - cb);
        for (int t = lane; t < m; t += 32) {
            int s = g_esrc[cb + t];
            float ex = __expf(fmaxf(g_ssrc[s] + sd, 0.f));
            denom += ex;
            stage[wslot][t] = make_float2(__int_as_float(s), ex);
        }
        __syncwarp();

        int k = 0;
        for (; k + 8 <= m; k += 8) {
            float2 p[8];
            uint2 v[8];
#pragma unroll
            for (int i = 0; i < 8; i++) p[i] = stage[wslot][k + i];
#pragma unroll
            for (int i = 0; i < 8; i++)
                v[i] = *(const uint2*)&hh[(size_t)__float_as_int(p[i].x) * D + lane * 4];
#pragma unroll
            for (int i = 0; i < 8; i++) {
                float2 a = __half22float2(*(__half2*)&v[i].x);
                float2 b = __half22float2(*(__half2*)&v[i].y);
                unsigned long long w = dup2(p[i].y);
                ffma2(acc0, w, *(unsigned long long*)&a);
                ffma2(acc1, w, *(unsigned long long*)&b);
            }
        }
        for (; k + 4 <= m; k += 4) {
            float2 p[4];
            uint2 v[4];
#pragma unroll
            for (int i = 0; i < 4; i++) p[i] = stage[wslot][k + i];
#pragma unroll
            for (int i = 0; i < 4; i++)
                v[i] = *(const uint2*)&hh[(size_t)__float_as_int(p[i].x) * D + lane * 4];
#pragma unroll
            for (int i = 0; i < 4; i++) {
                float2 a = __half22float2(*(__half2*)&v[i].x);
                float2 b = __half22float2(*(__half2*)&v[i].y);
                unsigned long long w = dup2(p[i].y);
                ffma2(acc0, w, *(unsigned long long*)&a);
                ffma2(acc1, w, *(unsigned long long*)&b);
            }
        }
        for (; k < m; k++) {
            float2 pk = stage[wslot][k];
            uint2 v = *(const uint2*)&hh[(size_t)__float_as_int(pk.x) * D + lane * 4];
            float2 a = __half22float2(*(__half2*)&v.x);
            float2 b = __half22float2(*(__half2*)&v.y);
            unsigned long long w = dup2(pk.y);
            ffma2(acc0, w, *(unsigned long long*)&a);
            ffma2(acc1, w, *(unsigned long long*)&b);
        }
        __syncwarp();
    }

#pragma unroll
    for (int o = 16; o; o >>= 1) denom += __shfl_xor_sync(0xffffffffu, denom, o);
    float inv = 1.f / denom;

    float2 lo = *(float2*)&acc0;
    float2 hi = *(float2*)&acc1;
    float4 b4 = *(const float4*)&bias[lane * 4];
    float4 o4;
    o4.x = lo.x * inv + b4.x;
    o4.y = lo.y * inv + b4.y;
    o4.z = hi.x * inv + b4.z;
    o4.w = hi.y * inv + b4.w;
    if (do_relu) {
        o4.x = fmaxf(o4.x, 0.f);
        o4.y = fmaxf(o4.y, 0.f);
        o4.z = fmaxf(o4.z, 0.f);
        o4.w = fmaxf(o4.w, 0.f);
    }
    *(float4*)&out[(size_t)node * D + lane * 4] = o4;
}

// ---------------------------------------------------------------- launch
extern "C" void kernel_launch(void* const* d_in, const int* in_sizes, int n_in,
                              void* d_out, int out_size) {
    const float* node_x = (const float*)d_in[0];
    const int*   ei     = (const int*)d_in[1];
    const float* W1     = (const float*)d_in[2];
    const float* as1    = (const float*)d_in[3];
    const float* ad1    = (const float*)d_in[4];
    const float* b1     = (const float*)d_in[5];
    const float* W2     = (const float*)d_in[6];
    const float* as2    = (const float*)d_in[7];
    const float* ad2    = (const float*)d_in[8];
    const float* b2     = (const float*)d_in[9];
    const float* Wout   = (const float*)d_in[10];
    const float* bout   = (const float*)d_in[11];
    float* out = (float*)d_out;

    int n = in_sizes[0] / D;       // 50000
    int E = in_sizes[1] / 2;       // 1600000

    float* x_ptr;
    __half *hh_ptr, *w16a_ptr, *w16b_ptr;
    int* deg_ptr;
    cudaGetSymbolAddress((void**)&x_ptr, g_x);
    cudaGetSymbolAddress((void**)&hh_ptr, g_hh);
    cudaGetSymbolAddress((void**)&w16a_ptr, g_w16a);
    cudaGetSymbolAddress((void**)&w16b_ptr, g_w16b);
    cudaGetSymbolAddress((void**)&deg_ptr, g_deg);

    const int SMEM_HMMA = (64 * XPAD + 128 * XPAD) * (int)sizeof(__half); // ~51 KB
    const int SMEM64 = (D * 64 + 32 * D) * (int)sizeof(float);            // 48 KB
    cudaFuncSetAttribute(hmma_gemm_kernel, cudaFuncAttributeMaxDynamicSharedMemorySize, SMEM_HMMA);
    cudaFuncSetAttribute(gemm_kernel<64>, cudaFuncAttributeMaxDynamicSharedMemorySize, SMEM64);

    int tot = E + n;
    int nb = (n + SCAN_B - 1) / SCAN_B;
    int agg_grid = (n * 32 + 255) / 256;
    int hmma_grid = (n + 63) / 64;
    int gemm_grid = (n + 31) / 32;

    // CSR build (+ W conversion folded into hist)
    cudaMemsetAsync(deg_ptr, 0, (size_t)n * sizeof(int), 0);
    hist_conv_kernel<<<CONV_BLOCKS + (tot + 2047) / 2048, 256>>>(ei, E, n, W1, W2);
    scan1_kernel<<<nb, SCAN_B>>>(n);
    scan3_kernel<<<nb, SCAN_B>>>(n, tot);
    scatter_kernel<<<(tot + 2047) / 2048, 256>>>(ei, E, n);

    // layer 1: HMMA GEMM + fused dots, then fused alpha+aggregate
    hmma_gemm_kernel<<<hmma_grid, 128, SMEM_HMMA>>>(node_x, w16a_ptr, hh_ptr, as1, ad1, n);
    gat_edge_kernel<<<agg_grid, 256>>>(hh_ptr, b1, x_ptr, n, 1);

    // layer 2
    hmma_gemm_kernel<<<hmma_grid, 128, SMEM_HMMA>>>(x_ptr, w16b_ptr, hh_ptr, as2, ad2, n);
    gat_edge_kernel<<<agg_grid, 256>>>(hh_ptr, b2, x_ptr, n, 0);

    // output linear (fp32 scalar)
    gemm_kernel<64><<<gemm_grid, 64, SMEM64>>>(x_ptr, Wout, bout, out, n);
}

// round 9
// speedup vs baseline: 1.5751x; 1.1489x over previous
#include <cuda_runtime.h>
#include <cuda_fp16.h>

// Problem shape (fixed per dataset)
#define NN   50000
#define EE_CAP 1650512   // E + N self loops, with margin
#define D    128
#define DOUT 64
#define SCAN_B 256
#define CONV_BLOCKS 96   // 64 blocks W1/W2 + 32 blocks Wout

// ---- device scratch (no allocation allowed) ----
__device__ __half g_hh[NN * D];     // fp16 transformed features for the edge gather
__device__ float  g_x[NN * D];      // aggregation output / next layer input
__device__ float  g_ssrc[NN];       // h @ att_src
__device__ float  g_sdst[NN];       // h @ att_dst
__device__ __half g_w16a[D * D];    // W1 in fp16
__device__ __half g_w16b[D * D];    // W2 in fp16
__device__ __half g_w16o[D * DOUT]; // W_out in fp16
__device__ int    g_deg[NN];
__device__ int    g_offs[NN + 1];
__device__ int    g_bsum[(NN + SCAN_B - 1) / SCAN_B];
__device__ int    g_rank[EE_CAP];   // per-edge rank within its destination
__device__ int    g_esrc[EE_CAP];   // CSR-by-dst: source node per edge

// packed f32x2 fma helpers
__device__ __forceinline__ void ffma2(unsigned long long& acc,
                                      unsigned long long a,
                                      unsigned long long b) {
    asm("fma.rn.f32x2 %0, %1, %2, %0;" : "+l"(acc) : "l"(a), "l"(b));
}
__device__ __forceinline__ unsigned long long dup2(float v) {
    unsigned long long r;
    asm("mov.b64 %0, {%1, %1};" : "=l"(r) : "f"(v));
    return r;
}

// ---------------------------------------------------------------- rank + W convert (merged)
// Blocks [0,64): convert W1/W2. Blocks [64,96): convert Wout.
// Remaining blocks: per-edge rank via one atomic (this IS the histogram too).
__global__ void rank_conv_kernel(const int* __restrict__ ei, int E, int n,
                                 const float* __restrict__ W1f,
                                 const float* __restrict__ W2f,
                                 const float* __restrict__ Wof) {
    if (blockIdx.x < 64) {
        int i = blockIdx.x * 256 + threadIdx.x;
        g_w16a[i] = __float2half_rn(W1f[i]);
        g_w16b[i] = __float2half_rn(W2f[i]);
        return;
    }
    if (blockIdx.x < CONV_BLOCKS) {
        int i = (blockIdx.x - 64) * 256 + threadIdx.x;
        if (i < D * DOUT) g_w16o[i] = __float2half_rn(Wof[i]);
        return;
    }
    int i0 = (((int)blockIdx.x - CONV_BLOCKS) * 256 + threadIdx.x) * 4;
#pragma unroll
    for (int u = 0; u < 4; u++) {
        int i = i0 + u;
        if (i < E) {
            g_rank[i] = atomicAdd(&g_deg[ei[E + i]], 1);
        } else if (i < E + n) {
            g_rank[i] = atomicAdd(&g_deg[i - E], 1);
        }
    }
}

// ---------------------------------------------------------------- scan (2 kernels)
__global__ void scan1_kernel(int n) {
    __shared__ int ws[SCAN_B / 32];
    int tid = threadIdx.x;
    int lane = tid & 31, wid = tid >> 5;
    int i = blockIdx.x * SCAN_B + tid;
    int v = (i < n) ? g_deg[i] : 0;
    int x = v;
#pragma unroll
    for (int o = 1; o < 32; o <<= 1) {
        int y = __shfl_up_sync(0xffffffffu, x, o);
        if (lane >= o) x += y;
    }
    if (lane == 31) ws[wid] = x;
    __syncthreads();
    int base = 0;
#pragma unroll
    for (int w = 0; w < SCAN_B / 32; w++)
        if (w < wid) base += ws[w];
    int ex = base + x - v;
    if (i < n) g_offs[i] = ex;
    if (tid == SCAN_B - 1) g_bsum[blockIdx.x] = ex + v;
}

__global__ void scan3_kernel(int n, int total) {
    __shared__ int wpart[SCAN_B / 32];
    int tid = threadIdx.x;
    int lane = tid & 31, wid = tid >> 5;
    int part = 0;
    for (int t = tid; t < (int)blockIdx.x; t += SCAN_B) part += g_bsum[t];
#pragma unroll
    for (int o = 16; o; o >>= 1) part += __shfl_xor_sync(0xffffffffu, part, o);
    if (lane == 0) wpart[wid] = part;
    __syncthreads();
    int base = 0;
#pragma unroll
    for (int w = 0; w < SCAN_B / 32; w++) base += wpart[w];

    int i = blockIdx.x * SCAN_B + tid;
    if (i < n) g_offs[i] += base;
    if (i == 0) g_offs[n] = total;
}

// ---------------------------------------------------------------- placement (no atomics)
__global__ void place_kernel(const int* __restrict__ ei, int E, int n) {
    int i0 = (blockIdx.x * blockDim.x + threadIdx.x) * 4;
#pragma unroll
    for (int u = 0; u < 4; u++) {
        int i = i0 + u;
        if (i < E) {
            int s = ei[i];
            int d = ei[E + i];
            g_esrc[g_offs[d] + g_rank[i]] = s;
        } else if (i < E + n) {
            int v = i - E;
            g_esrc[g_offs[v] + g_rank[i]] = v;
        }
    }
}

// ---------------------------------------------------------------- HMMA GEMM (GAT layers)
// hh_out[n,128] (fp16) = X[n,128] @ W16[128,128], fp32 accumulate via
// mma.sync.m16n8k16. Fused epilogue: per-row attention dots -> g_ssrc/g_sdst.
#define XPAD 136
__global__ void __launch_bounds__(128) hmma_gemm_kernel(
    const float* __restrict__ X, const __half* __restrict__ W16,
    __half* __restrict__ hh_out,
    const float* __restrict__ asrc, const float* __restrict__ adst, int n) {
    extern __shared__ __half smh[];
    __half* Xs = smh;                 // 64 x XPAD
    __half* Ws = smh + 64 * XPAD;     // 128 x XPAD
    int tid = threadIdx.x;
    int lane = tid & 31;
    int warp = tid >> 5;
    int rowbase = blockIdx.x * 64;

    for (int i = tid; i < D * D; i += 128)
        Ws[(i >> 7) * XPAD + (i & 127)] = W16[i];
    for (int i = tid; i < 64 * D; i += 128) {
        int r = rowbase + (i >> 7);
        Xs[(i >> 7) * XPAD + (i & 127)] =
            (r < n) ? __float2half_rn(X[(size_t)r * D + (i & 127)]) : __half(0.f);
    }
    __syncthreads();

    unsigned xs_base = (unsigned)__cvta_generic_to_shared(Xs);
    unsigned ws_base = (unsigned)__cvta_generic_to_shared(Ws);
    int warpRow = warp * 16;

    unsigned a[8][4];
#pragma unroll
    for (int ka = 0; ka < 8; ka++) {
        unsigned addr = xs_base +
            ((warpRow + (lane & 15)) * XPAD + ka * 16 + (lane >> 4) * 8) * 2;
        asm volatile("ldmatrix.sync.aligned.m8n8.x4.shared.b16 {%0,%1,%2,%3}, [%4];"
                     : "=r"(a[ka][0]), "=r"(a[ka][1]), "=r"(a[ka][2]), "=r"(a[ka][3])
                     : "r"(addr));
    }

    int g = lane >> 2;
    int c2 = (lane & 3) * 2;
    int rowLo = rowbase + warpRow + g;
    int rowHi = rowLo + 8;

    float psL = 0.f, psH = 0.f, qdL = 0.f, qdH = 0.f;

#pragma unroll
    for (int j = 0; j < 16; j++) {
        float d0 = 0.f, d1 = 0.f, d2 = 0.f, d3 = 0.f;
#pragma unroll
        for (int ka = 0; ka < 8; ka++) {
            unsigned b0, b1;
            unsigned baddr = ws_base + ((ka * 16 + (lane & 15)) * XPAD + j * 8) * 2;
            asm volatile("ldmatrix.sync.aligned.m8n8.x2.trans.shared.b16 {%0,%1}, [%2];"
                         : "=r"(b0), "=r"(b1) : "r"(baddr));
            asm volatile(
                "mma.sync.aligned.m16n8k16.row.col.f32.f16.f16.f32 "
                "{%0,%1,%2,%3}, {%4,%5,%6,%7}, {%8,%9}, {%0,%1,%2,%3};"
                : "+f"(d0), "+f"(d1), "+f"(d2), "+f"(d3)
                : "r"(a[ka][0]), "r"(a[ka][1]), "r"(a[ka][2]), "r"(a[ka][3]),
                  "r"(b0), "r"(b1));
        }
        int col = j * 8 + c2;
        float av0 = asrc[col], av1 = asrc[col + 1];
        float dv0 = adst[col], dv1 = adst[col + 1];
        psL += d0 * av0 + d1 * av1;
        psH += d2 * av0 + d3 * av1;
        qdL += d0 * dv0 + d1 * dv1;
        qdH += d2 * dv0 + d3 * dv1;
        if (rowLo < n) {
            __half2 hlo = __floats2half2_rn(d0, d1);
            *(__half2*)&hh_out[(size_t)rowLo * D + col] = hlo;
        }
        if (rowHi < n) {
            __half2 hhi = __floats2half2_rn(d2, d3);
            *(__half2*)&hh_out[(size_t)rowHi * D + col] = hhi;
        }
    }

    psL += __shfl_xor_sync(0xffffffffu, psL, 1);
    psL += __shfl_xor_sync(0xffffffffu, psL, 2);
    psH += __shfl_xor_sync(0xffffffffu, psH, 1);
    psH += __shfl_xor_sync(0xffffffffu, psH, 2);
    qdL += __shfl_xor_sync(0xffffffffu, qdL, 1);
    qdL += __shfl_xor_sync(0xffffffffu, qdL, 2);
    qdH += __shfl_xor_sync(0xffffffffu, qdH, 1);
    qdH += __shfl_xor_sync(0xffffffffu, qdH, 2);
    if ((lane & 3) == 0) {
        if (rowLo < n) { g_ssrc[rowLo] = psL; g_sdst[rowLo] = qdL; }
        if (rowHi < n) { g_ssrc[rowHi] = psH; g_sdst[rowHi] = qdH; }
    }
}

// ---------------------------------------------------------------- HMMA output GEMM
// Y[n,64] (fp32) = X[n,128] @ Wo16[128,64] + bias. Same tile scheme, 8 j-tiles.
#define WPAD 72
__global__ void __launch_bounds__(128) hmma_out_kernel(
    const float* __restrict__ X, const __half* __restrict__ Wo16,
    const float* __restrict__ bias, float* __restrict__ Y, int n) {
    extern __shared__ __half smh[];
    __half* Xs = smh;                 // 64 x XPAD
    __half* Ws = smh + 64 * XPAD;     // 128 x WPAD
    int tid = threadIdx.x;
    int lane = tid & 31;
    int warp = tid >> 5;
    int rowbase = blockIdx.x * 64;

    for (int i = tid; i < D * DOUT; i += 128)
        Ws[(i / DOUT) * WPAD + (i % DOUT)] = Wo16[i];
    for (int i = tid; i < 64 * D; i += 128) {
        int r = rowbase + (i >> 7);
        Xs[(i >> 7) * XPAD + (i & 127)] =
            (r < n) ? __float2half_rn(X[(size_t)r * D + (i & 127)]) : __half(0.f);
    }
    __syncthreads();

    unsigned xs_base = (unsigned)__cvta_generic_to_shared(Xs);
    unsigned ws_base = (unsigned)__cvta_generic_to_shared(Ws);
    int warpRow = warp * 16;

    unsigned a[8][4];
#pragma unroll
    for (int ka = 0; ka < 8; ka++) {
        unsigned addr = xs_base +
            ((warpRow + (lane & 15)) * XPAD + ka * 16 + (lane >> 4) * 8) * 2;
        asm volatile("ldmatrix.sync.aligned.m8n8.x4.shared.b16 {%0,%1,%2,%3}, [%4];"
                     : "=r"(a[ka][0]), "=r"(a[ka][1]), "=r"(a[ka][2]), "=r"(a[ka][3])
                     : "r"(addr));
    }

    int g = lane >> 2;
    int c2 = (lane & 3) * 2;
    int rowLo = rowbase + warpRow + g;
    int rowHi = rowLo + 8;

#pragma unroll
    for (int j = 0; j < 8; j++) {
        float d0 = 0.f, d1 = 0.f, d2 = 0.f, d3 = 0.f;
#pragma unroll
        for (int ka = 0; ka < 8; ka++) {
            unsigned b0, b1;
            unsigned baddr = ws_base + ((ka * 16 + (lane & 15)) * WPAD + j * 8) * 2;
            asm volatile("ldmatrix.sync.aligned.m8n8.x2.trans.shared.b16 {%0,%1}, [%2];"
                         : "=r"(b0), "=r"(b1) : "r"(baddr));
            asm volatile(
                "mma.sync.aligned.m16n8k16.row.col.f32.f16.f16.f32 "
                "{%0,%1,%2,%3}, {%4,%5,%6,%7}, {%8,%9}, {%0,%1,%2,%3};"
                : "+f"(d0), "+f"(d1), "+f"(d2), "+f"(d3)
                : "r"(a[ka][0]), "r"(a[ka][1]), "r"(a[ka][2]), "r"(a[ka][3]),
                  "r"(b0), "r"(b1));
        }
        int col = j * 8 + c2;
        float bb0 = bias[col], bb1 = bias[col + 1];
        if (rowLo < n) {
            float2 o = make_float2(d0 + bb0, d1 + bb1);
            *(float2*)&Y[(size_t)rowLo * DOUT + col] = o;
        }
        if (rowHi < n) {
            float2 o = make_float2(d2 + bb0, d3 + bb1);
            *(float2*)&Y[(size_t)rowHi * DOUT + col] = o;
        }
    }
}

// ---------------------------------------------------------------- fused alpha + aggregation
#define CH 64
__global__ void __launch_bounds__(256) gat_edge_kernel(
    const __half* __restrict__ hh, const float* __restrict__ bias,
    float* __restrict__ out, int n, int do_relu) {
    __shared__ float2 stage[8][CH];
    int gt = blockIdx.x * blockDim.x + threadIdx.x;
    int node = gt >> 5, lane = gt & 31;
    int wslot = (threadIdx.x >> 5);
    if (node >= n) return;

    int beg = g_offs[node];
    int end = g_offs[node + 1];
    float sd = g_sdst[node];

    float denom = 0.f;
    unsigned long long acc0 = 0ull, acc1 = 0ull;

    for (int cb = beg; cb < end; cb += CH) {
        int m = min(CH, end - cb);
        for (int t = lane; t < m; t += 32) {
            int s = g_esrc[cb + t];
            float ex = __expf(fmaxf(g_ssrc[s] + sd, 0.f));
            denom += ex;
            stage[wslot][t] = make_float2(__int_as_float(s), ex);
        }
        __syncwarp();

        int k = 0;
        for (; k + 8 <= m; k += 8) {
            float2 p[8];
            uint2 v[8];
#pragma unroll
            for (int i = 0; i < 8; i++) p[i] = stage[wslot][k + i];
#pragma unroll
            for (int i = 0; i < 8; i++)
                v[i] = *(const uint2*)&hh[(size_t)__float_as_int(p[i].x) * D + lane * 4];
#pragma unroll
            for (int i = 0; i < 8; i++) {
                float2 a = __half22float2(*(__half2*)&v[i].x);
                float2 b = __half22float2(*(__half2*)&v[i].y);
                unsigned long long w = dup2(p[i].y);
                ffma2(acc0, w, *(unsigned long long*)&a);
                ffma2(acc1, w, *(unsigned long long*)&b);
            }
        }
        for (; k + 4 <= m; k += 4) {
            float2 p[4];
            uint2 v[4];
#pragma unroll
            for (int i = 0; i < 4; i++) p[i] = stage[wslot][k + i];
#pragma unroll
            for (int i = 0; i < 4; i++)
                v[i] = *(const uint2*)&hh[(size_t)__float_as_int(p[i].x) * D + lane * 4];
#pragma unroll
            for (int i = 0; i < 4; i++) {
                float2 a = __half22float2(*(__half2*)&v[i].x);
                float2 b = __half22float2(*(__half2*)&v[i].y);
                unsigned long long w = dup2(p[i].y);
                ffma2(acc0, w, *(unsigned long long*)&a);
                ffma2(acc1, w, *(unsigned long long*)&b);
            }
        }
        for (; k < m; k++) {
            float2 pk = stage[wslot][k];
            uint2 v = *(const uint2*)&hh[(size_t)__float_as_int(pk.x) * D + lane * 4];
            float2 a = __half22float2(*(__half2*)&v.x);
            float2 b = __half22float2(*(__half2*)&v.y);
            unsigned long long w = dup2(pk.y);
            ffma2(acc0, w, *(unsigned long long*)&a);
            ffma2(acc1, w, *(unsigned long long*)&b);
        }
        __syncwarp();
    }

#pragma unroll
    for (int o = 16; o; o >>= 1) denom += __shfl_xor_sync(0xffffffffu, denom, o);
    float inv = 1.f / denom;

    float2 lo = *(float2*)&acc0;
    float2 hi = *(float2*)&acc1;
    float4 b4 = *(const float4*)&bias[lane * 4];
    float4 o4;
    o4.x = lo.x * inv + b4.x;
    o4.y = lo.y * inv + b4.y;
    o4.z = hi.x * inv + b4.z;
    o4.w = hi.y * inv + b4.w;
    if (do_relu) {
        o4.x = fmaxf(o4.x, 0.f);
        o4.y = fmaxf(o4.y, 0.f);
        o4.z = fmaxf(o4.z, 0.f);
        o4.w = fmaxf(o4.w, 0.f);
    }
    *(float4*)&out[(size_t)node * D + lane * 4] = o4;
}

// ---------------------------------------------------------------- launch
extern "C" void kernel_launch(void* const* d_in, const int* in_sizes, int n_in,
                              void* d_out, int out_size) {
    const float* node_x = (const float*)d_in[0];
    const int*   ei     = (const int*)d_in[1];
    const float* W1     = (const float*)d_in[2];
    const float* as1    = (const float*)d_in[3];
    const float* ad1    = (const float*)d_in[4];
    const float* b1     = (const float*)d_in[5];
    const float* W2     = (const float*)d_in[6];
    const float* as2    = (const float*)d_in[7];
    const float* ad2    = (const float*)d_in[8];
    const float* b2     = (const float*)d_in[9];
    const float* Wout   = (const float*)d_in[10];
    const float* bout   = (const float*)d_in[11];
    float* out = (float*)d_out;

    int n = in_sizes[0] / D;       // 50000
    int E = in_sizes[1] / 2;       // 1600000

    float* x_ptr;
    __half *hh_ptr, *w16a_ptr, *w16b_ptr, *w16o_ptr;
    int* deg_ptr;
    cudaGetSymbolAddress((void**)&x_ptr, g_x);
    cudaGetSymbolAddress((void**)&hh_ptr, g_hh);
    cudaGetSymbolAddress((void**)&w16a_ptr, g_w16a);
    cudaGetSymbolAddress((void**)&w16b_ptr, g_w16b);
    cudaGetSymbolAddress((void**)&w16o_ptr, g_w16o);
    cudaGetSymbolAddress((void**)&deg_ptr, g_deg);

    const int SMEM_HMMA = (64 * XPAD + 128 * XPAD) * (int)sizeof(__half); // ~51 KB
    const int SMEM_OUT  = (64 * XPAD + 128 * WPAD) * (int)sizeof(__half); // ~35 KB
    cudaFuncSetAttribute(hmma_gemm_kernel, cudaFuncAttributeMaxDynamicSharedMemorySize, SMEM_HMMA);
    cudaFuncSetAttribute(hmma_out_kernel, cudaFuncAttributeMaxDynamicSharedMemorySize, SMEM_OUT);

    int tot = E + n;
    int nb = (n + SCAN_B - 1) / SCAN_B;
    int agg_grid = (n * 32 + 255) / 256;
    int hmma_grid = (n + 63) / 64;

    // CSR build: one atomic pass (rank) + scan + placement (no atomics)
    cudaMemsetAsync(deg_ptr, 0, (size_t)n * sizeof(int), 0);
    rank_conv_kernel<<<CONV_BLOCKS + (tot + 1023) / 1024, 256>>>(ei, E, n, W1, W2, Wout);
    scan1_kernel<<<nb, SCAN_B>>>(n);
    scan3_kernel<<<nb, SCAN_B>>>(n, tot);
    place_kernel<<<(tot + 1023) / 1024, 256>>>(ei, E, n);

    // layer 1
    hmma_gemm_kernel<<<hmma_grid, 128, SMEM_HMMA>>>(node_x, w16a_ptr, hh_ptr, as1, ad1, n);
    gat_edge_kernel<<<agg_grid, 256>>>(hh_ptr, b1, x_ptr, n, 1);

    // layer 2
    hmma_gemm_kernel<<<hmma_grid, 128, SMEM_HMMA>>>(x_ptr, w16b_ptr, hh_ptr, as2, ad2, n);
    gat_edge_kernel<<<agg_grid, 256>>>(hh_ptr, b2, x_ptr, n, 0);

    // output linear (HMMA)
    hmma_out_kernel<<<hmma_grid, 128, SMEM_OUT>>>(x_ptr, w16o_ptr, bout, out, n);
}

// round 10
// speedup vs baseline: 1.6253x; 1.0319x over previous
#include <cuda_runtime.h>
#include <cuda_fp16.h>

// Problem shape (fixed per dataset)
#define NN   50000
#define EE_CAP 1650512   // E + N self loops, with margin
#define D    128
#define DOUT 64
#define SCAN_B 256
#define CONV_BLOCKS 96   // 64 blocks W1/W2 + 32 blocks Wout

// ---- device scratch (no allocation allowed) ----
__device__ __half g_hh[NN * D];     // fp16 transformed features for the edge gather
__device__ float  g_x[NN * D];      // aggregation output / next layer input
__device__ float  g_ssrc[NN];       // h @ att_src
__device__ float  g_sdst[NN];       // h @ att_dst
__device__ __half g_w16a[D * D];    // W1 in fp16
__device__ __half g_w16b[D * D];    // W2 in fp16
__device__ __half g_w16o[D * DOUT]; // W_out in fp16
__device__ int    g_deg[NN];        // zeroed at static init; re-zeroed by scan_kernel
__device__ int    g_offs[NN + 1];
__device__ int    g_bsum[(NN + SCAN_B - 1) / SCAN_B];
__device__ int    g_cnt;            // scan publish counter (reset by rank_conv)
__device__ int    g_rank[EE_CAP];   // per-edge rank within its destination
__device__ int    g_esrc[EE_CAP];   // CSR-by-dst: source node per edge

// packed f32x2 fma helpers
__device__ __forceinline__ void ffma2(unsigned long long& acc,
                                      unsigned long long a,
                                      unsigned long long b) {
    asm("fma.rn.f32x2 %0, %1, %2, %0;" : "+l"(acc) : "l"(a), "l"(b));
}
__device__ __forceinline__ unsigned long long dup2(float v) {
    unsigned long long r;
    asm("mov.b64 %0, {%1, %1};" : "=l"(r) : "f"(v));
    return r;
}

// ---------------------------------------------------------------- rank + W convert (merged)
// Blocks [0,64): convert W1/W2. Blocks [64,96): convert Wout (+ reset g_cnt).
// Remaining blocks: per-edge rank via one atomic (this IS the histogram too).
__global__ void rank_conv_kernel(const int* __restrict__ ei, int E, int n,
                                 const float* __restrict__ W1f,
                                 const float* __restrict__ W2f,
                                 const float* __restrict__ Wof) {
    if (blockIdx.x < 64) {
        int i = blockIdx.x * 256 + threadIdx.x;
        g_w16a[i] = __float2half_rn(W1f[i]);
        g_w16b[i] = __float2half_rn(W2f[i]);
        return;
    }
    if (blockIdx.x < CONV_BLOCKS) {
        int i = (blockIdx.x - 64) * 256 + threadIdx.x;
        if (i < D * DOUT) g_w16o[i] = __float2half_rn(Wof[i]);
        if (blockIdx.x == 64 && threadIdx.x == 0) g_cnt = 0;
        return;
    }
    int i0 = (((int)blockIdx.x - CONV_BLOCKS) * 256 + threadIdx.x) * 4;
    if (i0 + 3 < E && (E & 3) == 0) {
        int4 d4 = *(const int4*)&ei[E + i0];
        int4 r4;
        r4.x = atomicAdd(&g_deg[d4.x], 1);
        r4.y = atomicAdd(&g_deg[d4.y], 1);
        r4.z = atomicAdd(&g_deg[d4.z], 1);
        r4.w = atomicAdd(&g_deg[d4.w], 1);
        *(int4*)&g_rank[i0] = r4;
    } else {
#pragma unroll
        for (int u = 0; u < 4; u++) {
            int i = i0 + u;
            if (i < E) g_rank[i] = atomicAdd(&g_deg[ei[E + i]], 1);
            else if (i < E + n) g_rank[i] = atomicAdd(&g_deg[i - E], 1);
        }
    }
}

// ---------------------------------------------------------------- fused scan (single kernel)
// All nb (<=196) blocks are co-resident on the chip, so a counter-based join
// is deadlock-free. Phase 1: block-local exclusive scan, publish block sum.
// Phase 2: spin until all published, add prefix of preceding block sums.
// Also re-zeroes g_deg for the next replay.
__global__ void scan_kernel(int n, int total, int nb) {
    __shared__ int ws[SCAN_B / 32];
    __shared__ int s_part;
    int tid = threadIdx.x;
    int lane = tid & 31, wid = tid >> 5;
    int i = blockIdx.x * SCAN_B + tid;
    int v = 0;
    if (i < n) {
        v = g_deg[i];
        g_deg[i] = 0;                 // reset for next replay
    }
    int x = v;
#pragma unroll
    for (int o = 1; o < 32; o <<= 1) {
        int y = __shfl_up_sync(0xffffffffu, x, o);
        if (lane >= o) x += y;
    }
    if (lane == 31) ws[wid] = x;
    __syncthreads();
    int base = 0;
#pragma unroll
    for (int w = 0; w < SCAN_B / 32; w++)
        if (w < wid) base += ws[w];
    int ex = base + x - v;            // exclusive within block

    if (tid == SCAN_B - 1) {
        g_bsum[blockIdx.x] = ex + v;  // block total
        __threadfence();
        atomicAdd(&g_cnt, 1);
    }

    // join: wait until every block has published its sum
    if (tid == 0) {
        while (*(volatile int*)&g_cnt < nb) { }
    }
    __syncthreads();

    // prefix over preceding block sums (nb <= blockDim.x)
    int part = 0;
    if (tid < (int)blockIdx.x) part = __ldcg(&g_bsum[tid]);
#pragma unroll
    for (int o = 16; o; o >>= 1) part += __shfl_xor_sync(0xffffffffu, part, o);
    if (lane == 0) ws[wid] = part;
    __syncthreads();
    if (tid == 0) {
        int p = 0;
#pragma unroll
        for (int w = 0; w < SCAN_B / 32; w++) p += ws[w];
        s_part = p;
    }
    __syncthreads();

    if (i < n) g_offs[i] = ex + s_part;
    if (i == 0) g_offs[n] = total;
}

// ---------------------------------------------------------------- HMMA GEMM layer-1 (+ merged placement)
// Blocks [0, hmma_grid): GEMM + fused dots. Blocks >= hmma_grid: CSR
// placement (no atomics) — independent work, overlapped in one launch.
#define XPAD 136
#define PLACE_EPT 8    // edges per thread in the place portion (128 threads)
__global__ void __launch_bounds__(128) hmma_gemm_place_kernel(
    const float* __restrict__ X, const __half* __restrict__ W16,
    __half* __restrict__ hh_out,
    const float* __restrict__ asrc, const float* __restrict__ adst, int n,
    const int* __restrict__ ei, int E, int hmma_grid) {
    if ((int)blockIdx.x >= hmma_grid) {
        // ---- placement portion ----
        int pb = (int)blockIdx.x - hmma_grid;
        int i0 = (pb * 128 + (int)threadIdx.x) * PLACE_EPT;
#pragma unroll
        for (int q = 0; q < PLACE_EPT; q += 4) {
            int ib = i0 + q;
            if (ib + 3 < E && (E & 3) == 0) {
                int4 s4 = *(const int4*)&ei[ib];
                int4 d4 = *(const int4*)&ei[E + ib];
                int4 r4 = *(const int4*)&g_rank[ib];
                g_esrc[g_offs[d4.x] + r4.x] = s4.x;
                g_esrc[g_offs[d4.y] + r4.y] = s4.y;
                g_esrc[g_offs[d4.z] + r4.z] = s4.z;
                g_esrc[g_offs[d4.w] + r4.w] = s4.w;
            } else {
#pragma unroll
                for (int u = 0; u < 4; u++) {
                    int i = ib + u;
                    if (i < E) {
                        g_esrc[g_offs[ei[E + i]] + g_rank[i]] = ei[i];
                    } else if (i < E + n) {
                        int v = i - E;
                        g_esrc[g_offs[v] + g_rank[i]] = v;
                    }
                }
            }
        }
        return;
    }

    // ---- HMMA GEMM portion ----
    extern __shared__ __half smh[];
    __half* Xs = smh;                 // 64 x XPAD
    __half* Ws = smh + 64 * XPAD;     // 128 x XPAD
    int tid = threadIdx.x;
    int lane = tid & 31;
    int warp = tid >> 5;
    int rowbase = blockIdx.x * 64;

    for (int i = tid; i < D * D; i += 128)
        Ws[(i >> 7) * XPAD + (i & 127)] = W16[i];
    for (int i = tid; i < 64 * D; i += 128) {
        int r = rowbase + (i >> 7);
        Xs[(i >> 7) * XPAD + (i & 127)] =
            (r < n) ? __float2half_rn(X[(size_t)r * D + (i & 127)]) : __half(0.f);
    }
    __syncthreads();

    unsigned xs_base = (unsigned)__cvta_generic_to_shared(Xs);
    unsigned ws_base = (unsigned)__cvta_generic_to_shared(Ws);
    int warpRow = warp * 16;

    unsigned a[8][4];
#pragma unroll
    for (int ka = 0; ka < 8; ka++) {
        unsigned addr = xs_base +
            ((warpRow + (lane & 15)) * XPAD + ka * 16 + (lane >> 4) * 8) * 2;
        asm volatile("ldmatrix.sync.aligned.m8n8.x4.shared.b16 {%0,%1,%2,%3}, [%4];"
                     : "=r"(a[ka][0]), "=r"(a[ka][1]), "=r"(a[ka][2]), "=r"(a[ka][3])
                     : "r"(addr));
    }

    int g = lane >> 2;
    int c2 = (lane & 3) * 2;
    int rowLo = rowbase + warpRow + g;
    int rowHi = rowLo + 8;

    float psL = 0.f, psH = 0.f, qdL = 0.f, qdH = 0.f;

#pragma unroll
    for (int j = 0; j < 16; j++) {
        float d0 = 0.f, d1 = 0.f, d2 = 0.f, d3 = 0.f;
#pragma unroll
        for (int ka = 0; ka < 8; ka++) {
            unsigned b0, b1;
            unsigned baddr = ws_base + ((ka * 16 + (lane & 15)) * XPAD + j * 8) * 2;
            asm volatile("ldmatrix.sync.aligned.m8n8.x2.trans.shared.b16 {%0,%1}, [%2];"
                         : "=r"(b0), "=r"(b1) : "r"(baddr));
            asm volatile(
                "mma.sync.aligned.m16n8k16.row.col.f32.f16.f16.f32 "
                "{%0,%1,%2,%3}, {%4,%5,%6,%7}, {%8,%9}, {%0,%1,%2,%3};"
                : "+f"(d0), "+f"(d1), "+f"(d2), "+f"(d3)
                : "r"(a[ka][0]), "r"(a[ka][1]), "r"(a[ka][2]), "r"(a[ka][3]),
                  "r"(b0), "r"(b1));
        }
        int col = j * 8 + c2;
        float av0 = asrc[col], av1 = asrc[col + 1];
        float dv0 = adst[col], dv1 = adst[col + 1];
        psL += d0 * av0 + d1 * av1;
        psH += d2 * av0 + d3 * av1;
        qdL += d0 * dv0 + d1 * dv1;
        qdH += d2 * dv0 + d3 * dv1;
        if (rowLo < n) {
            __half2 hlo = __floats2half2_rn(d0, d1);
            *(__half2*)&hh_out[(size_t)rowLo * D + col] = hlo;
        }
        if (rowHi < n) {
            __half2 hhi = __floats2half2_rn(d2, d3);
            *(__half2*)&hh_out[(size_t)rowHi * D + col] = hhi;
        }
    }

    psL += __shfl_xor_sync(0xffffffffu, psL, 1);
    psL += __shfl_xor_sync(0xffffffffu, psL, 2);
    psH += __shfl_xor_sync(0xffffffffu, psH, 1);
    psH += __shfl_xor_sync(0xffffffffu, psH, 2);
    qdL += __shfl_xor_sync(0xffffffffu, qdL, 1);
    qdL += __shfl_xor_sync(0xffffffffu, qdL, 2);
    qdH += __shfl_xor_sync(0xffffffffu, qdH, 1);
    qdH += __shfl_xor_sync(0xffffffffu, qdH, 2);
    if ((lane & 3) == 0) {
        if (rowLo < n) { g_ssrc[rowLo] = psL; g_sdst[rowLo] = qdL; }
        if (rowHi < n) { g_ssrc[rowHi] = psH; g_sdst[rowHi] = qdH; }
    }
}

// ---------------------------------------------------------------- HMMA GEMM (layer 2, no place)
__global__ void __launch_bounds__(128) hmma_gemm_kernel(
    const float* __restrict__ X, const __half* __restrict__ W16,
    __half* __restrict__ hh_out,
    const float* __restrict__ asrc, const float* __restrict__ adst, int n) {
    extern __shared__ __half smh[];
    __half* Xs = smh;
    __half* Ws = smh + 64 * XPAD;
    int tid = threadIdx.x;
    int lane = tid & 31;
    int warp = tid >> 5;
    int rowbase = blockIdx.x * 64;

    for (int i = tid; i < D * D; i += 128)
        Ws[(i >> 7) * XPAD + (i & 127)] = W16[i];
    for (int i = tid; i < 64 * D; i += 128) {
        int r = rowbase + (i >> 7);
        Xs[(i >> 7) * XPAD + (i & 127)] =
            (r < n) ? __float2half_rn(X[(size_t)r * D + (i & 127)]) : __half(0.f);
    }
    __syncthreads();

    unsigned xs_base = (unsigned)__cvta_generic_to_shared(Xs);
    unsigned ws_base = (unsigned)__cvta_generic_to_shared(Ws);
    int warpRow = warp * 16;

    unsigned a[8][4];
#pragma unroll
    for (int ka = 0; ka < 8; ka++) {
        unsigned addr = xs_base +
            ((warpRow + (lane & 15)) * XPAD + ka * 16 + (lane >> 4) * 8) * 2;
        asm volatile("ldmatrix.sync.aligned.m8n8.x4.shared.b16 {%0,%1,%2,%3}, [%4];"
                     : "=r"(a[ka][0]), "=r"(a[ka][1]), "=r"(a[ka][2]), "=r"(a[ka][3])
                     : "r"(addr));
    }

    int g = lane >> 2;
    int c2 = (lane & 3) * 2;
    int rowLo = rowbase + warpRow + g;
    int rowHi = rowLo + 8;

    float psL = 0.f, psH = 0.f, qdL = 0.f, qdH = 0.f;

#pragma unroll
    for (int j = 0; j < 16; j++) {
        float d0 = 0.f, d1 = 0.f, d2 = 0.f, d3 = 0.f;
#pragma unroll
        for (int ka = 0; ka < 8; ka++) {
            unsigned b0, b1;
            unsigned baddr = ws_base + ((ka * 16 + (lane & 15)) * XPAD + j * 8) * 2;
            asm volatile("ldmatrix.sync.aligned.m8n8.x2.trans.shared.b16 {%0,%1}, [%2];"
                         : "=r"(b0), "=r"(b1) : "r"(baddr));
            asm volatile(
                "mma.sync.aligned.m16n8k16.row.col.f32.f16.f16.f32 "
                "{%0,%1,%2,%3}, {%4,%5,%6,%7}, {%8,%9}, {%0,%1,%2,%3};"
                : "+f"(d0), "+f"(d1), "+f"(d2), "+f"(d3)
                : "r"(a[ka][0]), "r"(a[ka][1]), "r"(a[ka][2]), "r"(a[ka][3]),
                  "r"(b0), "r"(b1));
        }
        int col = j * 8 + c2;
        float av0 = asrc[col], av1 = asrc[col + 1];
        float dv0 = adst[col], dv1 = adst[col + 1];
        psL += d0 * av0 + d1 * av1;
        psH += d2 * av0 + d3 * av1;
        qdL += d0 * dv0 + d1 * dv1;
        qdH += d2 * dv0 + d3 * dv1;
        if (rowLo < n) {
            __half2 hlo = __floats2half2_rn(d0, d1);
            *(__half2*)&hh_out[(size_t)rowLo * D + col] = hlo;
        }
        if (rowHi < n) {
            __half2 hhi = __floats2half2_rn(d2, d3);
            *(__half2*)&hh_out[(size_t)rowHi * D + col] = hhi;
        }
    }

    psL += __shfl_xor_sync(0xffffffffu, psL, 1);
    psL += __shfl_xor_sync(0xffffffffu, psL, 2);
    psH += __shfl_xor_sync(0xffffffffu, psH, 1);
    psH += __shfl_xor_sync(0xffffffffu, psH, 2);
    qdL += __shfl_xor_sync(0xffffffffu, qdL, 1);
    qdL += __shfl_xor_sync(0xffffffffu, qdL, 2);
    qdH += __shfl_xor_sync(0xffffffffu, qdH, 1);
    qdH += __shfl_xor_sync(0xffffffffu, qdH, 2);
    if ((lane & 3) == 0) {
        if (rowLo < n) { g_ssrc[rowLo] = psL; g_sdst[rowLo] = qdL; }
        if (rowHi < n) { g_ssrc[rowHi] = psH; g_sdst[rowHi] = qdH; }
    }
}

// ---------------------------------------------------------------- HMMA output GEMM
#define WPAD 72
__global__ void __launch_bounds__(128) hmma_out_kernel(
    const float* __restrict__ X, const __half* __restrict__ Wo16,
    const float* __restrict__ bias, float* __restrict__ Y, int n) {
    extern __shared__ __half smh[];
    __half* Xs = smh;
    __half* Ws = smh + 64 * XPAD;
    int tid = threadIdx.x;
    int lane = tid & 31;
    int warp = tid >> 5;
    int rowbase = blockIdx.x * 64;

    for (int i = tid; i < D * DOUT; i += 128)
        Ws[(i / DOUT) * WPAD + (i % DOUT)] = Wo16[i];
    for (int i = tid; i < 64 * D; i += 128) {
        int r = rowbase + (i >> 7);
        Xs[(i >> 7) * XPAD + (i & 127)] =
            (r < n) ? __float2half_rn(X[(size_t)r * D + (i & 127)]) : __half(0.f);
    }
    __syncthreads();

    unsigned xs_base = (unsigned)__cvta_generic_to_shared(Xs);
    unsigned ws_base = (unsigned)__cvta_generic_to_shared(Ws);
    int warpRow = warp * 16;

    unsigned a[8][4];
#pragma unroll
    for (int ka = 0; ka < 8; ka++) {
        unsigned addr = xs_base +
            ((warpRow + (lane & 15)) * XPAD + ka * 16 + (lane >> 4) * 8) * 2;
        asm volatile("ldmatrix.sync.aligned.m8n8.x4.shared.b16 {%0,%1,%2,%3}, [%4];"
                     : "=r"(a[ka][0]), "=r"(a[ka][1]), "=r"(a[ka][2]), "=r"(a[ka][3])
                     : "r"(addr));
    }

    int g = lane >> 2;
    int c2 = (lane & 3) * 2;
    int rowLo = rowbase + warpRow + g;
    int rowHi = rowLo + 8;

#pragma unroll
    for (int j = 0; j < 8; j++) {
        float d0 = 0.f, d1 = 0.f, d2 = 0.f, d3 = 0.f;
#pragma unroll
        for (int ka = 0; ka < 8; ka++) {
            unsigned b0, b1;
            unsigned baddr = ws_base + ((ka * 16 + (lane & 15)) * WPAD + j * 8) * 2;
            asm volatile("ldmatrix.sync.aligned.m8n8.x2.trans.shared.b16 {%0,%1}, [%2];"
                         : "=r"(b0), "=r"(b1) : "r"(baddr));
            asm volatile(
                "mma.sync.aligned.m16n8k16.row.col.f32.f16.f16.f32 "
                "{%0,%1,%2,%3}, {%4,%5,%6,%7}, {%8,%9}, {%0,%1,%2,%3};"
                : "+f"(d0), "+f"(d1), "+f"(d2), "+f"(d3)
                : "r"(a[ka][0]), "r"(a[ka][1]), "r"(a[ka][2]), "r"(a[ka][3]),
                  "r"(b0), "r"(b1));
        }
        int col = j * 8 + c2;
        float bb0 = bias[col], bb1 = bias[col + 1];
        if (rowLo < n) {
            float2 o = make_float2(d0 + bb0, d1 + bb1);
            *(float2*)&Y[(size_t)rowLo * DOUT + col] = o;
        }
        if (rowHi < n) {
            float2 o = make_float2(d2 + bb0, d3 + bb1);
            *(float2*)&Y[(size_t)rowHi * DOUT + col] = o;
        }
    }
}

// ---------------------------------------------------------------- fused alpha + aggregation
#define CH 64
__global__ void __launch_bounds__(256) gat_edge_kernel(
    const __half* __restrict__ hh, const float* __restrict__ bias,
    float* __restrict__ out, int n, int do_relu) {
    __shared__ float2 stage[8][CH];
    int gt = blockIdx.x * blockDim.x + threadIdx.x;
    int node = gt >> 5, lane = gt & 31;
    int wslot = (threadIdx.x >> 5);
    if (node >= n) return;

    int beg = g_offs[node];
    int end = g_offs[node + 1];
    float sd = g_sdst[node];

    float denom = 0.f;
    unsigned long long acc0 = 0ull, acc1 = 0ull;

    for (int cb = beg; cb < end; cb += CH) {
        int m = min(CH, end - cb);
        for (int t = lane; t < m; t += 32) {
            int s = g_esrc[cb + t];
            float ex = __expf(fmaxf(g_ssrc[s] + sd, 0.f));
            denom += ex;
            stage[wslot][t] = make_float2(__int_as_float(s), ex);
        }
        __syncwarp();

        int k = 0;
        for (; k + 8 <= m; k += 8) {
            float2 p[8];
            uint2 v[8];
#pragma unroll
            for (int i = 0; i < 8; i++) p[i] = stage[wslot][k + i];
#pragma unroll
            for (int i = 0; i < 8; i++)
                v[i] = *(const uint2*)&hh[(size_t)__float_as_int(p[i].x) * D + lane * 4];
#pragma unroll
            for (int i = 0; i < 8; i++) {
                float2 a = __half22float2(*(__half2*)&v[i].x);
                float2 b = __half22float2(*(__half2*)&v[i].y);
                unsigned long long w = dup2(p[i].y);
                ffma2(acc0, w, *(unsigned long long*)&a);
                ffma2(acc1, w, *(unsigned long long*)&b);
            }
        }
        for (; k < m; k++) {
            float2 pk = stage[wslot][k];
            uint2 v = *(const uint2*)&hh[(size_t)__float_as_int(pk.x) * D + lane * 4];
            float2 a = __half22float2(*(__half2*)&v.x);
            float2 b = __half22float2(*(__half2*)&v.y);
            unsigned long long w = dup2(pk.y);
            ffma2(acc0, w, *(unsigned long long*)&a);
            ffma2(acc1, w, *(unsigned long long*)&b);
        }
        __syncwarp();
    }

#pragma unroll
    for (int o = 16; o; o >>= 1) denom += __shfl_xor_sync(0xffffffffu, denom, o);
    float inv = 1.f / denom;

    float2 lo = *(float2*)&acc0;
    float2 hi = *(float2*)&acc1;
    float4 b4 = *(const float4*)&bias[lane * 4];
    float4 o4;
    o4.x = lo.x * inv + b4.x;
    o4.y = lo.y * inv + b4.y;
    o4.z = hi.x * inv + b4.z;
    o4.w = hi.y * inv + b4.w;
    if (do_relu) {
        o4.x = fmaxf(o4.x, 0.f);
        o4.y = fmaxf(o4.y, 0.f);
        o4.z = fmaxf(o4.z, 0.f);
        o4.w = fmaxf(o4.w, 0.f);
    }
    *(float4*)&out[(size_t)node * D + lane * 4] = o4;
}

// ---------------------------------------------------------------- launch
extern "C" void kernel_launch(void* const* d_in, const int* in_sizes, int n_in,
                              void* d_out, int out_size) {
    const float* node_x = (const float*)d_in[0];
    const int*   ei     = (const int*)d_in[1];
    const float* W1     = (const float*)d_in[2];
    const float* as1    = (const float*)d_in[3];
    const float* ad1    = (const float*)d_in[4];
    const float* b1     = (const float*)d_in[5];
    const float* W2     = (const float*)d_in[6];
    const float* as2    = (const float*)d_in[7];
    const float* ad2    = (const float*)d_in[8];
    const float* b2     = (const float*)d_in[9];
    const float* Wout   = (const float*)d_in[10];
    const float* bout   = (const float*)d_in[11];
    float* out = (float*)d_out;

    int n = in_sizes[0] / D;       // 50000
    int E = in_sizes[1] / 2;       // 1600000

    float* x_ptr;
    __half *hh_ptr, *w16a_ptr, *w16b_ptr, *w16o_ptr;
    cudaGetSymbolAddress((void**)&x_ptr, g_x);
    cudaGetSymbolAddress((void**)&hh_ptr, g_hh);
    cudaGetSymbolAddress((void**)&w16a_ptr, g_w16a);
    cudaGetSymbolAddress((void**)&w16b_ptr, g_w16b);
    cudaGetSymbolAddress((void**)&w16o_ptr, g_w16o);

    const int SMEM_HMMA = (64 * XPAD + 128 * XPAD) * (int)sizeof(__half); // ~51 KB
    const int SMEM_OUT  = (64 * XPAD + 128 * WPAD) * (int)sizeof(__half); // ~35 KB
    cudaFuncSetAttribute(hmma_gemm_place_kernel, cudaFuncAttributeMaxDynamicSharedMemorySize, SMEM_HMMA);
    cudaFuncSetAttribute(hmma_gemm_kernel, cudaFuncAttributeMaxDynamicSharedMemorySize, SMEM_HMMA);
    cudaFuncSetAttribute(hmma_out_kernel, cudaFuncAttributeMaxDynamicSharedMemorySize, SMEM_OUT);

    int tot = E + n;
    int nb = (n + SCAN_B - 1) / SCAN_B;
    int agg_grid = (n * 32 + 255) / 256;
    int hmma_grid = (n + 63) / 64;
    int place_blocks = (tot + 128 * PLACE_EPT - 1) / (128 * PLACE_EPT);

    // CSR rank (+ W conversion + counter reset)
    rank_conv_kernel<<<CONV_BLOCKS + (tot + 1023) / 1024, 256>>>(ei, E, n, W1, W2, Wout);
    // fused scan (also re-zeroes g_deg)
    scan_kernel<<<nb, SCAN_B>>>(n, tot, nb);

    // layer-1 GEMM + placement merged in one launch
    hmma_gemm_place_kernel<<<hmma_grid + place_blocks, 128, SMEM_HMMA>>>(
        node_x, w16a_ptr, hh_ptr, as1, ad1, n, ei, E, hmma_grid);
    gat_edge_kernel<<<agg_grid, 256>>>(hh_ptr, b1, x_ptr, n, 1);

    // layer 2
    hmma_gemm_kernel<<<hmma_grid, 128, SMEM_HMMA>>>(x_ptr, w16b_ptr, hh_ptr, as2, ad2, n);
    gat_edge_kernel<<<agg_grid, 256>>>(hh_ptr, b2, x_ptr, n, 0);

    // output linear (HMMA)
    hmma_out_kernel<<<hmma_grid, 128, SMEM_OUT>>>(x_ptr, w16o_ptr, bout, out, n);
}

// round 11
// speedup vs baseline: 1.7111x; 1.0528x over previous
#include <cuda_runtime.h>
#include <cuda_fp16.h>

// Problem shape (fixed per dataset)
#define NN   50000
#define EE_CAP 1650512   // E + N self loops, with margin
#define D    128
#define DOUT 64
#define SCAN_B 256
#define CONV_BLOCKS 96   // 64 blocks W1/W2 + 32 blocks Wout

// ---- device scratch (no allocation allowed) ----
__device__ __half g_hh[NN * D];     // fp16 transformed features for the edge gather
__device__ float  g_x[NN * D];      // aggregation output / next layer input
__device__ float  g_ssrc[NN];       // h @ att_src
__device__ float  g_sdst[NN];       // h @ att_dst
__device__ __half g_w16a[D * D];    // W1 in fp16
__device__ __half g_w16b[D * D];    // W2 in fp16
__device__ __half g_w16o[D * DOUT]; // W_out in fp16
__device__ int    g_deg[NN];        // zeroed at static init; re-zeroed by scan_kernel
__device__ int    g_offs[NN + 1];
__device__ int    g_bsum[(NN + SCAN_B - 1) / SCAN_B];
__device__ int    g_cnt;            // scan publish counter (reset by rank_conv)
__device__ int    g_rank[EE_CAP];   // per edge: (rank << 16) | dst
__device__ int    g_esrc[EE_CAP];   // CSR-by-dst: source node per edge

// packed f32x2 fma helpers
__device__ __forceinline__ void ffma2(unsigned long long& acc,
                                      unsigned long long a,
                                      unsigned long long b) {
    asm("fma.rn.f32x2 %0, %1, %2, %0;" : "+l"(acc) : "l"(a), "l"(b));
}
__device__ __forceinline__ unsigned long long dup2(float v) {
    unsigned long long r;
    asm("mov.b64 %0, {%1, %1};" : "=l"(r) : "f"(v));
    return r;
}

// ---------------------------------------------------------------- rank + W convert (merged)
// Blocks [0,64): convert W1/W2. Blocks [64,96): convert Wout (+ reset g_cnt).
// Remaining blocks: per-edge rank via one atomic (this IS the histogram too).
// Pack (rank << 16) | dst so placement never re-reads the dst row.
__global__ void rank_conv_kernel(const int* __restrict__ ei, int E, int n,
                                 const float* __restrict__ W1f,
                                 const float* __restrict__ W2f,
                                 const float* __restrict__ Wof) {
    if (blockIdx.x < 64) {
        int i = blockIdx.x * 256 + threadIdx.x;
        g_w16a[i] = __float2half_rn(W1f[i]);
        g_w16b[i] = __float2half_rn(W2f[i]);
        return;
    }
    if (blockIdx.x < CONV_BLOCKS) {
        int i = (blockIdx.x - 64) * 256 + threadIdx.x;
        if (i < D * DOUT) g_w16o[i] = __float2half_rn(Wof[i]);
        if (blockIdx.x == 64 && threadIdx.x == 0) g_cnt = 0;
        return;
    }
    int i0 = (((int)blockIdx.x - CONV_BLOCKS) * 256 + threadIdx.x) * 4;
    if (i0 + 3 < E && (E & 3) == 0) {
        int4 d4 = *(const int4*)&ei[E + i0];
        int4 r4;
        r4.x = (atomicAdd(&g_deg[d4.x], 1) << 16) | d4.x;
        r4.y = (atomicAdd(&g_deg[d4.y], 1) << 16) | d4.y;
        r4.z = (atomicAdd(&g_deg[d4.z], 1) << 16) | d4.z;
        r4.w = (atomicAdd(&g_deg[d4.w], 1) << 16) | d4.w;
        *(int4*)&g_rank[i0] = r4;
    } else {
#pragma unroll
        for (int u = 0; u < 4; u++) {
            int i = i0 + u;
            if (i < E) {
                int d = ei[E + i];
                g_rank[i] = (atomicAdd(&g_deg[d], 1) << 16) | d;
            } else if (i < E + n) {
                int v = i - E;
                g_rank[i] = (atomicAdd(&g_deg[v], 1) << 16) | v;
            }
        }
    }
}

// ---------------------------------------------------------------- fused scan (single kernel)
// All nb (<=196) blocks co-resident -> counter join is deadlock-free.
// Also re-zeroes g_deg for the next replay.
__global__ void scan_kernel(int n, int total, int nb) {
    __shared__ int ws[SCAN_B / 32];
    __shared__ int s_part;
    int tid = threadIdx.x;
    int lane = tid & 31, wid = tid >> 5;
    int i = blockIdx.x * SCAN_B + tid;
    int v = 0;
    if (i < n) {
        v = g_deg[i];
        g_deg[i] = 0;
    }
    int x = v;
#pragma unroll
    for (int o = 1; o < 32; o <<= 1) {
        int y = __shfl_up_sync(0xffffffffu, x, o);
        if (lane >= o) x += y;
    }
    if (lane == 31) ws[wid] = x;
    __syncthreads();
    int base = 0;
#pragma unroll
    for (int w = 0; w < SCAN_B / 32; w++)
        if (w < wid) base += ws[w];
    int ex = base + x - v;

    if (tid == SCAN_B - 1) {
        g_bsum[blockIdx.x] = ex + v;
        __threadfence();
        atomicAdd(&g_cnt, 1);
    }
    if (tid == 0) {
        while (*(volatile int*)&g_cnt < nb) { }
    }
    __syncthreads();

    int part = 0;
    if (tid < (int)blockIdx.x) part = __ldcg(&g_bsum[tid]);
#pragma unroll
    for (int o = 16; o; o >>= 1) part += __shfl_xor_sync(0xffffffffu, part, o);
    if (lane == 0) ws[wid] = part;
    __syncthreads();
    if (tid == 0) {
        int p = 0;
#pragma unroll
        for (int w = 0; w < SCAN_B / 32; w++) p += ws[w];
        s_part = p;
    }
    __syncthreads();

    if (i < n) g_offs[i] = ex + s_part;
    if (i == 0) g_offs[n] = total;
}

// ---------------------------------------------------------------- HMMA GEMM layer-1 (+ merged placement)
#define XPAD 136
#define PLACE_EPT 8
__global__ void __launch_bounds__(128) hmma_gemm_place_kernel(
    const float* __restrict__ X, const __half* __restrict__ W16,
    __half* __restrict__ hh_out,
    const float* __restrict__ asrc, const float* __restrict__ adst, int n,
    const int* __restrict__ ei, int E, int hmma_grid) {
    if ((int)blockIdx.x >= hmma_grid) {
        // ---- placement portion (no atomics, no dst re-read) ----
        int pb = (int)blockIdx.x - hmma_grid;
        int i0 = (pb * 128 + (int)threadIdx.x) * PLACE_EPT;
#pragma unroll
        for (int q = 0; q < PLACE_EPT; q += 4) {
            int ib = i0 + q;
            if (ib + 3 < E && (E & 3) == 0) {
                int4 s4 = *(const int4*)&ei[ib];
                int4 r4 = *(const int4*)&g_rank[ib];
                g_esrc[g_offs[r4.x & 0xFFFF] + (r4.x >> 16)] = s4.x;
                g_esrc[g_offs[r4.y & 0xFFFF] + (r4.y >> 16)] = s4.y;
                g_esrc[g_offs[r4.z & 0xFFFF] + (r4.z >> 16)] = s4.z;
                g_esrc[g_offs[r4.w & 0xFFFF] + (r4.w >> 16)] = s4.w;
            } else {
#pragma unroll
                for (int u = 0; u < 4; u++) {
                    int i = ib + u;
                    if (i < E) {
                        int pk = g_rank[i];
                        g_esrc[g_offs[pk & 0xFFFF] + (pk >> 16)] = ei[i];
                    } else if (i < E + n) {
                        int pk = g_rank[i];
                        g_esrc[g_offs[pk & 0xFFFF] + (pk >> 16)] = i - E;
                    }
                }
            }
        }
        return;
    }

    // ---- HMMA GEMM portion ----
    extern __shared__ __half smh[];
    __half* Xs = smh;                 // 64 x XPAD
    __half* Ws = smh + 64 * XPAD;     // 128 x XPAD
    int tid = threadIdx.x;
    int lane = tid & 31;
    int warp = tid >> 5;
    int rowbase = blockIdx.x * 64;

    for (int i = tid; i < D * D; i += 128)
        Ws[(i >> 7) * XPAD + (i & 127)] = W16[i];
    for (int i = tid; i < 64 * D; i += 128) {
        int r = rowbase + (i >> 7);
        Xs[(i >> 7) * XPAD + (i & 127)] =
            (r < n) ? __float2half_rn(X[(size_t)r * D + (i & 127)]) : __half(0.f);
    }
    __syncthreads();

    unsigned xs_base = (unsigned)__cvta_generic_to_shared(Xs);
    unsigned ws_base = (unsigned)__cvta_generic_to_shared(Ws);
    int warpRow = warp * 16;

    unsigned a[8][4];
#pragma unroll
    for (int ka = 0; ka < 8; ka++) {
        unsigned addr = xs_base +
            ((warpRow + (lane & 15)) * XPAD + ka * 16 + (lane >> 4) * 8) * 2;
        asm volatile("ldmatrix.sync.aligned.m8n8.x4.shared.b16 {%0,%1,%2,%3}, [%4];"
                     : "=r"(a[ka][0]), "=r"(a[ka][1]), "=r"(a[ka][2]), "=r"(a[ka][3])
                     : "r"(addr));
    }

    int g = lane >> 2;
    int c2 = (lane & 3) * 2;
    int rowLo = rowbase + warpRow + g;
    int rowHi = rowLo + 8;

    float psL = 0.f, psH = 0.f, qdL = 0.f, qdH = 0.f;

#pragma unroll
    for (int j = 0; j < 16; j++) {
        float d0 = 0.f, d1 = 0.f, d2 = 0.f, d3 = 0.f;
#pragma unroll
        for (int ka = 0; ka < 8; ka++) {
            unsigned b0, b1;
            unsigned baddr = ws_base + ((ka * 16 + (lane & 15)) * XPAD + j * 8) * 2;
            asm volatile("ldmatrix.sync.aligned.m8n8.x2.trans.shared.b16 {%0,%1}, [%2];"
                         : "=r"(b0), "=r"(b1) : "r"(baddr));
            asm volatile(
                "mma.sync.aligned.m16n8k16.row.col.f32.f16.f16.f32 "
                "{%0,%1,%2,%3}, {%4,%5,%6,%7}, {%8,%9}, {%0,%1,%2,%3};"
                : "+f"(d0), "+f"(d1), "+f"(d2), "+f"(d3)
                : "r"(a[ka][0]), "r"(a[ka][1]), "r"(a[ka][2]), "r"(a[ka][3]),
                  "r"(b0), "r"(b1));
        }
        int col = j * 8 + c2;
        float av0 = asrc[col], av1 = asrc[col + 1];
        float dv0 = adst[col], dv1 = adst[col + 1];
        psL += d0 * av0 + d1 * av1;
        psH += d2 * av0 + d3 * av1;
        qdL += d0 * dv0 + d1 * dv1;
        qdH += d2 * dv0 + d3 * dv1;
        if (rowLo < n) {
            __half2 hlo = __floats2half2_rn(d0, d1);
            *(__half2*)&hh_out[(size_t)rowLo * D + col] = hlo;
        }
        if (rowHi < n) {
            __half2 hhi = __floats2half2_rn(d2, d3);
            *(__half2*)&hh_out[(size_t)rowHi * D + col] = hhi;
        }
    }

    psL += __shfl_xor_sync(0xffffffffu, psL, 1);
    psL += __shfl_xor_sync(0xffffffffu, psL, 2);
    psH += __shfl_xor_sync(0xffffffffu, psH, 1);
    psH += __shfl_xor_sync(0xffffffffu, psH, 2);
    qdL += __shfl_xor_sync(0xffffffffu, qdL, 1);
    qdL += __shfl_xor_sync(0xffffffffu, qdL, 2);
    qdH += __shfl_xor_sync(0xffffffffu, qdH, 1);
    qdH += __shfl_xor_sync(0xffffffffu, qdH, 2);
    if ((lane & 3) == 0) {
        if (rowLo < n) { g_ssrc[rowLo] = psL; g_sdst[rowLo] = qdL; }
        if (rowHi < n) { g_ssrc[rowHi] = psH; g_sdst[rowHi] = qdH; }
    }
}

// ---------------------------------------------------------------- HMMA GEMM (layer 2)
__global__ void __launch_bounds__(128) hmma_gemm_kernel(
    const float* __restrict__ X, const __half* __restrict__ W16,
    __half* __restrict__ hh_out,
    const float* __restrict__ asrc, const float* __restrict__ adst, int n) {
    extern __shared__ __half smh[];
    __half* Xs = smh;
    __half* Ws = smh + 64 * XPAD;
    int tid = threadIdx.x;
    int lane = tid & 31;
    int warp = tid >> 5;
    int rowbase = blockIdx.x * 64;

    for (int i = tid; i < D * D; i += 128)
        Ws[(i >> 7) * XPAD + (i & 127)] = W16[i];
    for (int i = tid; i < 64 * D; i += 128) {
        int r = rowbase + (i >> 7);
        Xs[(i >> 7) * XPAD + (i & 127)] =
            (r < n) ? __float2half_rn(X[(size_t)r * D + (i & 127)]) : __half(0.f);
    }
    __syncthreads();

    unsigned xs_base = (unsigned)__cvta_generic_to_shared(Xs);
    unsigned ws_base = (unsigned)__cvta_generic_to_shared(Ws);
    int warpRow = warp * 16;

    unsigned a[8][4];
#pragma unroll
    for (int ka = 0; ka < 8; ka++) {
        unsigned addr = xs_base +
            ((warpRow + (lane & 15)) * XPAD + ka * 16 + (lane >> 4) * 8) * 2;
        asm volatile("ldmatrix.sync.aligned.m8n8.x4.shared.b16 {%0,%1,%2,%3}, [%4];"
                     : "=r"(a[ka][0]), "=r"(a[ka][1]), "=r"(a[ka][2]), "=r"(a[ka][3])
                     : "r"(addr));
    }

    int g = lane >> 2;
    int c2 = (lane & 3) * 2;
    int rowLo = rowbase + warpRow + g;
    int rowHi = rowLo + 8;

    float psL = 0.f, psH = 0.f, qdL = 0.f, qdH = 0.f;

#pragma unroll
    for (int j = 0; j < 16; j++) {
        float d0 = 0.f, d1 = 0.f, d2 = 0.f, d3 = 0.f;
#pragma unroll
        for (int ka = 0; ka < 8; ka++) {
            unsigned b0, b1;
            unsigned baddr = ws_base + ((ka * 16 + (lane & 15)) * XPAD + j * 8) * 2;
            asm volatile("ldmatrix.sync.aligned.m8n8.x2.trans.shared.b16 {%0,%1}, [%2];"
                         : "=r"(b0), "=r"(b1) : "r"(baddr));
            asm volatile(
                "mma.sync.aligned.m16n8k16.row.col.f32.f16.f16.f32 "
                "{%0,%1,%2,%3}, {%4,%5,%6,%7}, {%8,%9}, {%0,%1,%2,%3};"
                : "+f"(d0), "+f"(d1), "+f"(d2), "+f"(d3)
                : "r"(a[ka][0]), "r"(a[ka][1]), "r"(a[ka][2]), "r"(a[ka][3]),
                  "r"(b0), "r"(b1));
        }
        int col = j * 8 + c2;
        float av0 = asrc[col], av1 = asrc[col + 1];
        float dv0 = adst[col], dv1 = adst[col + 1];
        psL += d0 * av0 + d1 * av1;
        psH += d2 * av0 + d3 * av1;
        qdL += d0 * dv0 + d1 * dv1;
        qdH += d2 * dv0 + d3 * dv1;
        if (rowLo < n) {
            __half2 hlo = __floats2half2_rn(d0, d1);
            *(__half2*)&hh_out[(size_t)rowLo * D + col] = hlo;
        }
        if (rowHi < n) {
            __half2 hhi = __floats2half2_rn(d2, d3);
            *(__half2*)&hh_out[(size_t)rowHi * D + col] = hhi;
        }
    }

    psL += __shfl_xor_sync(0xffffffffu, psL, 1);
    psL += __shfl_xor_sync(0xffffffffu, psL, 2);
    psH += __shfl_xor_sync(0xffffffffu, psH, 1);
    psH += __shfl_xor_sync(0xffffffffu, psH, 2);
    qdL += __shfl_xor_sync(0xffffffffu, qdL, 1);
    qdL += __shfl_xor_sync(0xffffffffu, qdL, 2);
    qdH += __shfl_xor_sync(0xffffffffu, qdH, 1);
    qdH += __shfl_xor_sync(0xffffffffu, qdH, 2);
    if ((lane & 3) == 0) {
        if (rowLo < n) { g_ssrc[rowLo] = psL; g_sdst[rowLo] = qdL; }
        if (rowHi < n) { g_ssrc[rowHi] = psH; g_sdst[rowHi] = qdH; }
    }
}

// ---------------------------------------------------------------- HMMA output GEMM
#define WPAD 72
__global__ void __launch_bounds__(128) hmma_out_kernel(
    const float* __restrict__ X, const __half* __restrict__ Wo16,
    const float* __restrict__ bias, float* __restrict__ Y, int n) {
    extern __shared__ __half smh[];
    __half* Xs = smh;
    __half* Ws = smh + 64 * XPAD;
    int tid = threadIdx.x;
    int lane = tid & 31;
    int warp = tid >> 5;
    int rowbase = blockIdx.x * 64;

    for (int i = tid; i < D * DOUT; i += 128)
        Ws[(i / DOUT) * WPAD + (i % DOUT)] = Wo16[i];
    for (int i = tid; i < 64 * D; i += 128) {
        int r = rowbase + (i >> 7);
        Xs[(i >> 7) * XPAD + (i & 127)] =
            (r < n) ? __float2half_rn(X[(size_t)r * D + (i & 127)]) : __half(0.f);
    }
    __syncthreads();

    unsigned xs_base = (unsigned)__cvta_generic_to_shared(Xs);
    unsigned ws_base = (unsigned)__cvta_generic_to_shared(Ws);
    int warpRow = warp * 16;

    unsigned a[8][4];
#pragma unroll
    for (int ka = 0; ka < 8; ka++) {
        unsigned addr = xs_base +
            ((warpRow + (lane & 15)) * XPAD + ka * 16 + (lane >> 4) * 8) * 2;
        asm volatile("ldmatrix.sync.aligned.m8n8.x4.shared.b16 {%0,%1,%2,%3}, [%4];"
                     : "=r"(a[ka][0]), "=r"(a[ka][1]), "=r"(a[ka][2]), "=r"(a[ka][3])
                     : "r"(addr));
    }

    int g = lane >> 2;
    int c2 = (lane & 3) * 2;
    int rowLo = rowbase + warpRow + g;
    int rowHi = rowLo + 8;

#pragma unroll
    for (int j = 0; j < 8; j++) {
        float d0 = 0.f, d1 = 0.f, d2 = 0.f, d3 = 0.f;
#pragma unroll
        for (int ka = 0; ka < 8; ka++) {
            unsigned b0, b1;
            unsigned baddr = ws_base + ((ka * 16 + (lane & 15)) * WPAD + j * 8) * 2;
            asm volatile("ldmatrix.sync.aligned.m8n8.x2.trans.shared.b16 {%0,%1}, [%2];"
                         : "=r"(b0), "=r"(b1) : "r"(baddr));
            asm volatile(
                "mma.sync.aligned.m16n8k16.row.col.f32.f16.f16.f32 "
                "{%0,%1,%2,%3}, {%4,%5,%6,%7}, {%8,%9}, {%0,%1,%2,%3};"
                : "+f"(d0), "+f"(d1), "+f"(d2), "+f"(d3)
                : "r"(a[ka][0]), "r"(a[ka][1]), "r"(a[ka][2]), "r"(a[ka][3]),
                  "r"(b0), "r"(b1));
        }
        int col = j * 8 + c2;
        float bb0 = bias[col], bb1 = bias[col + 1];
        if (rowLo < n) {
            float2 o = make_float2(d0 + bb0, d1 + bb1);
            *(float2*)&Y[(size_t)rowLo * DOUT + col] = o;
        }
        if (rowHi < n) {
            float2 o = make_float2(d2 + bb0, d3 + bb1);
            *(float2*)&Y[(size_t)rowHi * DOUT + col] = o;
        }
    }
}

// ---------------------------------------------------------------- fused alpha + aggregation
// One warp per destination node. Staging: lanes compute exp(relu(e))
// (NEG_SLOPE=0 => e>=0, max-shift unnecessary), store {src byte-offset, ex}.
// Consumption: EDGE PAIRS — lanes 0-15 handle one edge's 128-half row (uint4,
// 8 halves per lane), lanes 16-31 the next edge. Halves per-edge instruction
// count vs the 32-lane/edge scheme. Cross-half merge via shfl in epilogue.
#define CH 64
__global__ void __launch_bounds__(256) gat_edge_kernel(
    const __half* __restrict__ hh, const float* __restrict__ bias,
    float* __restrict__ out, int n, int do_relu) {
    __shared__ float2 stage[8][CH];
    int gt = blockIdx.x * blockDim.x + threadIdx.x;
    int node = gt >> 5, lane = gt & 31;
    int wslot = (threadIdx.x >> 5);
    if (node >= n) return;

    int beg = g_offs[node];
    int end = g_offs[node + 1];
    float sd = g_sdst[node];
    int h = lane >> 4;            // half-warp: which edge of the pair
    int lane8 = lane & 15;        // feature subgroup (8 halves)
    const char* hbase = (const char*)hh + lane8 * 16;

    float denom = 0.f;
    unsigned long long acc0 = 0ull, acc1 = 0ull, acc2 = 0ull, acc3 = 0ull;

    for (int cb = beg; cb < end; cb += CH) {
        int m = min(CH, end - cb);
        for (int t = lane; t < m; t += 32) {
            int s = g_esrc[cb + t];
            float ex = __expf(fmaxf(g_ssrc[s] + sd, 0.f));
            denom += ex;
            stage[wslot][t] = make_float2(__int_as_float(s << 8), ex);  // byte offset
        }
        if ((m & 1) && lane == 0)                 // pad odd tail with zero-weight dup
            stage[wslot][m] = make_float2(stage[wslot][0].x, 0.f);
        __syncwarp();

        int mp = (m + 1) & ~1;
        int k = 0;
        for (; k + 8 <= mp; k += 8) {
            float2 p0 = stage[wslot][k + 0 + h];
            float2 p1 = stage[wslot][k + 2 + h];
            float2 p2 = stage[wslot][k + 4 + h];
            float2 p3 = stage[wslot][k + 6 + h];
            uint4 v0 = *(const uint4*)(hbase + (unsigned)__float_as_int(p0.x));
            uint4 v1 = *(const uint4*)(hbase + (unsigned)__float_as_int(p1.x));
            uint4 v2 = *(const uint4*)(hbase + (unsigned)__float_as_int(p2.x));
            uint4 v3 = *(const uint4*)(hbase + (unsigned)__float_as_int(p3.x));
#define EDGE_STEP(vv, ww) do { \
                unsigned long long w_ = dup2(ww); \
                float2 a0_ = __half22float2(*(__half2*)&(vv).x); \
                float2 a1_ = __half22float2(*(__half2*)&(vv).y); \
                float2 a2_ = __half22float2(*(__half2*)&(vv).z); \
                float2 a3_ = __half22float2(*(__half2*)&(vv).w); \
                ffma2(acc0, w_, *(unsigned long long*)&a0_); \
                ffma2(acc1, w_, *(unsigned long long*)&a1_); \
                ffma2(acc2, w_, *(unsigned long long*)&a2_); \
                ffma2(acc3, w_, *(unsigned long long*)&a3_); \
            } while (0)
            EDGE_STEP(v0, p0.y);
            EDGE_STEP(v1, p1.y);
            EDGE_STEP(v2, p2.y);
            EDGE_STEP(v3, p3.y);
        }
        for (; k < mp; k += 2) {
            float2 p = stage[wslot][k + h];
            uint4 v = *(const uint4*)(hbase + (unsigned)__float_as_int(p.x));
            EDGE_STEP(v, p.y);
        }
#undef EDGE_STEP
        __syncwarp();
    }

#pragma unroll
    for (int o = 16; o; o >>= 1) denom += __shfl_xor_sync(0xffffffffu, denom, o);
    float inv = 1.f / denom;

    // merge the two half-warps' accumulators (same feature slots)
    float2 f0 = *(float2*)&acc0;
    float2 f1 = *(float2*)&acc1;
    float2 f2 = *(float2*)&acc2;
    float2 f3 = *(float2*)&acc3;
    f0.x += __shfl_xor_sync(0xffffffffu, f0.x, 16);
    f0.y += __shfl_xor_sync(0xffffffffu, f0.y, 16);
    f1.x += __shfl_xor_sync(0xffffffffu, f1.x, 16);
    f1.y += __shfl_xor_sync(0xffffffffu, f1.y, 16);
    f2.x += __shfl_xor_sync(0xffffffffu, f2.x, 16);
    f2.y += __shfl_xor_sync(0xffffffffu, f2.y, 16);
    f3.x += __shfl_xor_sync(0xffffffffu, f3.x, 16);
    f3.y += __shfl_xor_sync(0xffffffffu, f3.y, 16);

    if (h == 0) {
        int fb = lane8 * 8;
        float4 b0 = *(const float4*)&bias[fb];
        float4 b1 = *(const float4*)&bias[fb + 4];
        float4 o0, o1;
        o0.x = f0.x * inv + b0.x;
        o0.y = f0.y * inv + b0.y;
        o0.z = f1.x * inv + b0.z;
        o0.w = f1.y * inv + b0.w;
        o1.x = f2.x * inv + b1.x;
        o1.y = f2.y * inv + b1.y;
        o1.z = f3.x * inv + b1.z;
        o1.w = f3.y * inv + b1.w;
        if (do_relu) {
            o0.x = fmaxf(o0.x, 0.f); o0.y = fmaxf(o0.y, 0.f);
            o0.z = fmaxf(o0.z, 0.f); o0.w = fmaxf(o0.w, 0.f);
            o1.x = fmaxf(o1.x, 0.f); o1.y = fmaxf(o1.y, 0.f);
            o1.z = fmaxf(o1.z, 0.f); o1.w = fmaxf(o1.w, 0.f);
        }
        *(float4*)&out[(size_t)node * D + fb] = o0;
        *(float4*)&out[(size_t)node * D + fb + 4] = o1;
    }
}

// ---------------------------------------------------------------- launch
extern "C" void kernel_launch(void* const* d_in, const int* in_sizes, int n_in,
                              void* d_out, int out_size) {
    const float* node_x = (const float*)d_in[0];
    const int*   ei     = (const int*)d_in[1];
    const float* W1     = (const float*)d_in[2];
    const float* as1    = (const float*)d_in[3];
    const float* ad1    = (const float*)d_in[4];
    const float* b1     = (const float*)d_in[5];
    const float* W2     = (const float*)d_in[6];
    const float* as2    = (const float*)d_in[7];
    const float* ad2    = (const float*)d_in[8];
    const float* b2     = (const float*)d_in[9];
    const float* Wout   = (const float*)d_in[10];
    const float* bout   = (const float*)d_in[11];
    float* out = (float*)d_out;

    int n = in_sizes[0] / D;       // 50000
    int E = in_sizes[1] / 2;       // 1600000

    float* x_ptr;
    __half *hh_ptr, *w16a_ptr, *w16b_ptr, *w16o_ptr;
    cudaGetSymbolAddress((void**)&x_ptr, g_x);
    cudaGetSymbolAddress((void**)&hh_ptr, g_hh);
    cudaGetSymbolAddress((void**)&w16a_ptr, g_w16a);
    cudaGetSymbolAddress((void**)&w16b_ptr, g_w16b);
    cudaGetSymbolAddress((void**)&w16o_ptr, g_w16o);

    const int SMEM_HMMA = (64 * XPAD + 128 * XPAD) * (int)sizeof(__half); // ~51 KB
    const int SMEM_OUT  = (64 * XPAD + 128 * WPAD) * (int)sizeof(__half); // ~35 KB
    cudaFuncSetAttribute(hmma_gemm_place_kernel, cudaFuncAttributeMaxDynamicSharedMemorySize, SMEM_HMMA);
    cudaFuncSetAttribute(hmma_gemm_kernel, cudaFuncAttributeMaxDynamicSharedMemorySize, SMEM_HMMA);
    cudaFuncSetAttribute(hmma_out_kernel, cudaFuncAttributeMaxDynamicSharedMemorySize, SMEM_OUT);

    int tot = E + n;
    int nb = (n + SCAN_B - 1) / SCAN_B;
    int agg_grid = (n * 32 + 255) / 256;
    int hmma_grid = (n + 63) / 64;
    int place_blocks = (tot + 128 * PLACE_EPT - 1) / (128 * PLACE_EPT);

    // CSR rank (+ W conversion + counter reset)
    rank_conv_kernel<<<CONV_BLOCKS + (tot + 1023) / 1024, 256>>>(ei, E, n, W1, W2, Wout);
    // fused scan (also re-zeroes g_deg)
    scan_kernel<<<nb, SCAN_B>>>(n, tot, nb);

    // layer-1 GEMM + placement merged
    hmma_gemm_place_kernel<<<hmma_grid + place_blocks, 128, SMEM_HMMA>>>(
        node_x, w16a_ptr, hh_ptr, as1, ad1, n, ei, E, hmma_grid);
    gat_edge_kernel<<<agg_grid, 256>>>(hh_ptr, b1, x_ptr, n, 1);

    // layer 2
    hmma_gemm_kernel<<<hmma_grid, 128, SMEM_HMMA>>>(x_ptr, w16b_ptr, hh_ptr, as2, ad2, n);
    gat_edge_kernel<<<agg_grid, 256>>>(hh_ptr, b2, x_ptr, n, 0);

    // output linear (HMMA)
    hmma_out_kernel<<<hmma_grid, 128, SMEM_OUT>>>(x_ptr, w16o_ptr, bout, out, n);
}

// round 12
// speedup vs baseline: 1.7418x; 1.0180x over previous
#include <cuda_runtime.h>
#include <cuda_fp16.h>

// Problem shape (fixed per dataset)
#define NN   50000
#define EE_CAP 1650512   // E + N self loops, with margin
#define D    128
#define DOUT 64
#define SCAN_B 256
#define CONV_BLOCKS 96   // 64 blocks W1/W2 + 32 blocks Wout

// ---- device scratch (no allocation allowed) ----
__device__ __half g_hh[NN * D];     // fp16 transformed features for the edge gather
__device__ float  g_x[NN * D];      // aggregation output / next layer input
__device__ float  g_ssrc[NN];       // h @ att_src
__device__ float  g_sdst[NN];       // h @ att_dst
__device__ __half g_w16a[D * D];    // W1 in fp16
__device__ __half g_w16b[D * D];    // W2 in fp16
__device__ __half g_w16o[D * DOUT]; // W_out in fp16
__device__ int    g_deg[NN];        // zeroed at static init; re-zeroed by scan portion
__device__ int    g_offs[NN + 1];
__device__ int    g_bsum[(NN + SCAN_B - 1) / SCAN_B];
__device__ int    g_cnt;            // scan publish counter  (reset by hmma_out)
__device__ int    g_cnt_rank;       // rank completion counter (reset by hmma_out)
__device__ int    g_rank[EE_CAP];   // per edge: (rank << 16) | dst
__device__ int    g_esrc[EE_CAP];   // CSR-by-dst: source node per edge

// packed f32x2 fma helpers
__device__ __forceinline__ void ffma2(unsigned long long& acc,
                                      unsigned long long a,
                                      unsigned long long b) {
    asm("fma.rn.f32x2 %0, %1, %2, %0;" : "+l"(acc) : "l"(a), "l"(b));
}
__device__ __forceinline__ unsigned long long dup2(float v) {
    unsigned long long r;
    asm("mov.b64 %0, {%1, %1};" : "=l"(r) : "f"(v));
    return r;
}

// ---------------------------------------------------------------- rank + W convert + scan (one launch)
// Blocks [0,64): convert W1/W2. Blocks [64,96): convert Wout.
// Blocks [96, 96+RB): per-edge rank via one atomic; publish completion.
// Blocks [96+RB, ...): scan — spin until all rank blocks done, then
// two-phase prefix over g_deg (also re-zeroes g_deg for the next replay).
__global__ void rank_scan_kernel(const int* __restrict__ ei, int E, int n,
                                 const float* __restrict__ W1f,
                                 const float* __restrict__ W2f,
                                 const float* __restrict__ Wof,
                                 int RB, int nb, int total) {
    if (blockIdx.x < 64) {
        int i = blockIdx.x * 256 + threadIdx.x;
        g_w16a[i] = __float2half_rn(W1f[i]);
        g_w16b[i] = __float2half_rn(W2f[i]);
        return;
    }
    if (blockIdx.x < CONV_BLOCKS) {
        int i = (blockIdx.x - 64) * 256 + threadIdx.x;
        if (i < D * DOUT) g_w16o[i] = __float2half_rn(Wof[i]);
        return;
    }
    if ((int)blockIdx.x < CONV_BLOCKS + RB) {
        // ---- rank portion ----
        int i0 = (((int)blockIdx.x - CONV_BLOCKS) * 256 + threadIdx.x) * 4;
        if (i0 + 3 < E && (E & 3) == 0) {
            int4 d4 = *(const int4*)&ei[E + i0];
            int4 r4;
            r4.x = (atomicAdd(&g_deg[d4.x], 1) << 16) | d4.x;
            r4.y = (atomicAdd(&g_deg[d4.y], 1) << 16) | d4.y;
            r4.z = (atomicAdd(&g_deg[d4.z], 1) << 16) | d4.z;
            r4.w = (atomicAdd(&g_deg[d4.w], 1) << 16) | d4.w;
            *(int4*)&g_rank[i0] = r4;
        } else {
#pragma unroll
            for (int u = 0; u < 4; u++) {
                int i = i0 + u;
                if (i < E) {
                    int d = ei[E + i];
                    g_rank[i] = (atomicAdd(&g_deg[d], 1) << 16) | d;
                } else if (i < E + n) {
                    int v = i - E;
                    g_rank[i] = (atomicAdd(&g_deg[v], 1) << 16) | v;
                }
            }
        }
        __syncthreads();
        if (threadIdx.x == 0) {
            __threadfence();
            atomicAdd(&g_cnt_rank, 1);
        }
        return;
    }

    // ---- scan portion ----
    __shared__ int ws[SCAN_B / 32];
    __shared__ int s_part;
    int sb = (int)blockIdx.x - CONV_BLOCKS - RB;
    int tid = threadIdx.x;
    int lane = tid & 31, wid = tid >> 5;

    if (tid == 0) {
        while (*(volatile int*)&g_cnt_rank < RB) { }
    }
    __syncthreads();
    __threadfence();   // acquire: make rank's g_deg writes visible

    int i = sb * SCAN_B + tid;
    int v = 0;
    if (i < n) {
        v = g_deg[i];
        g_deg[i] = 0;                 // reset for next replay
    }
    int x = v;
#pragma unroll
    for (int o = 1; o < 32; o <<= 1) {
        int y = __shfl_up_sync(0xffffffffu, x, o);
        if (lane >= o) x += y;
    }
    if (lane == 31) ws[wid] = x;
    __syncthreads();
    int base = 0;
#pragma unroll
    for (int w = 0; w < SCAN_B / 32; w++)
        if (w < wid) base += ws[w];
    int ex = base + x - v;

    if (tid == SCAN_B - 1) {
        g_bsum[sb] = ex + v;
        __threadfence();
        atomicAdd(&g_cnt, 1);
    }
    if (tid == 0) {
        while (*(volatile int*)&g_cnt < nb) { }
    }
    __syncthreads();

    int part = 0;
    if (tid < sb) part = __ldcg(&g_bsum[tid]);
#pragma unroll
    for (int o = 16; o; o >>= 1) part += __shfl_xor_sync(0xffffffffu, part, o);
    if (lane == 0) ws[wid] = part;
    __syncthreads();
    if (tid == 0) {
        int p = 0;
#pragma unroll
        for (int w = 0; w < SCAN_B / 32; w++) p += ws[w];
        s_part = p;
    }
    __syncthreads();

    if (i < n) g_offs[i] = ex + s_part;
    if (i == 0) g_offs[n] = total;
}

// ---------------------------------------------------------------- HMMA GEMM layer-1 (+ merged placement)
#define XPAD 136
#define PLACE_EPT 8
__global__ void __launch_bounds__(128) hmma_gemm_place_kernel(
    const float* __restrict__ X, const __half* __restrict__ W16,
    __half* __restrict__ hh_out,
    const float* __restrict__ asrc, const float* __restrict__ adst, int n,
    const int* __restrict__ ei, int E, int hmma_grid) {
    if ((int)blockIdx.x >= hmma_grid) {
        // ---- placement portion (no atomics, no dst re-read) ----
        int pb = (int)blockIdx.x - hmma_grid;
        int i0 = (pb * 128 + (int)threadIdx.x) * PLACE_EPT;
#pragma unroll
        for (int q = 0; q < PLACE_EPT; q += 4) {
            int ib = i0 + q;
            if (ib + 3 < E && (E & 3) == 0) {
                int4 s4 = *(const int4*)&ei[ib];
                int4 r4 = *(const int4*)&g_rank[ib];
                g_esrc[g_offs[r4.x & 0xFFFF] + (r4.x >> 16)] = s4.x;
                g_esrc[g_offs[r4.y & 0xFFFF] + (r4.y >> 16)] = s4.y;
                g_esrc[g_offs[r4.z & 0xFFFF] + (r4.z >> 16)] = s4.z;
                g_esrc[g_offs[r4.w & 0xFFFF] + (r4.w >> 16)] = s4.w;
            } else {
#pragma unroll
                for (int u = 0; u < 4; u++) {
                    int i = ib + u;
                    if (i < E) {
                        int pk = g_rank[i];
                        g_esrc[g_offs[pk & 0xFFFF] + (pk >> 16)] = ei[i];
                    } else if (i < E + n) {
                        int pk = g_rank[i];
                        g_esrc[g_offs[pk & 0xFFFF] + (pk >> 16)] = i - E;
                    }
                }
            }
        }
        return;
    }

    // ---- HMMA GEMM portion ----
    extern __shared__ __half smh[];
    __half* Xs = smh;                 // 64 x XPAD
    __half* Ws = smh + 64 * XPAD;     // 128 x XPAD
    int tid = threadIdx.x;
    int lane = tid & 31;
    int warp = tid >> 5;
    int rowbase = blockIdx.x * 64;

    for (int i = tid; i < D * D; i += 128)
        Ws[(i >> 7) * XPAD + (i & 127)] = W16[i];
    for (int i = tid; i < 64 * D; i += 128) {
        int r = rowbase + (i >> 7);
        Xs[(i >> 7) * XPAD + (i & 127)] =
            (r < n) ? __float2half_rn(X[(size_t)r * D + (i & 127)]) : __half(0.f);
    }
    __syncthreads();

    unsigned xs_base = (unsigned)__cvta_generic_to_shared(Xs);
    unsigned ws_base = (unsigned)__cvta_generic_to_shared(Ws);
    int warpRow = warp * 16;

    unsigned a[8][4];
#pragma unroll
    for (int ka = 0; ka < 8; ka++) {
        unsigned addr = xs_base +
            ((warpRow + (lane & 15)) * XPAD + ka * 16 + (lane >> 4) * 8) * 2;
        asm volatile("ldmatrix.sync.aligned.m8n8.x4.shared.b16 {%0,%1,%2,%3}, [%4];"
                     : "=r"(a[ka][0]), "=r"(a[ka][1]), "=r"(a[ka][2]), "=r"(a[ka][3])
                     : "r"(addr));
    }

    int g = lane >> 2;
    int c2 = (lane & 3) * 2;
    int rowLo = rowbase + warpRow + g;
    int rowHi = rowLo + 8;

    float psL = 0.f, psH = 0.f, qdL = 0.f, qdH = 0.f;

#pragma unroll
    for (int j = 0; j < 16; j++) {
        float d0 = 0.f, d1 = 0.f, d2 = 0.f, d3 = 0.f;
#pragma unroll
        for (int ka = 0; ka < 8; ka++) {
            unsigned b0, b1;
            unsigned baddr = ws_base + ((ka * 16 + (lane & 15)) * XPAD + j * 8) * 2;
            asm volatile("ldmatrix.sync.aligned.m8n8.x2.trans.shared.b16 {%0,%1}, [%2];"
                         : "=r"(b0), "=r"(b1) : "r"(baddr));
            asm volatile(
                "mma.sync.aligned.m16n8k16.row.col.f32.f16.f16.f32 "
                "{%0,%1,%2,%3}, {%4,%5,%6,%7}, {%8,%9}, {%0,%1,%2,%3};"
                : "+f"(d0), "+f"(d1), "+f"(d2), "+f"(d3)
                : "r"(a[ka][0]), "r"(a[ka][1]), "r"(a[ka][2]), "r"(a[ka][3]),
                  "r"(b0), "r"(b1));
        }
        int col = j * 8 + c2;
        float av0 = asrc[col], av1 = asrc[col + 1];
        float dv0 = adst[col], dv1 = adst[col + 1];
        psL += d0 * av0 + d1 * av1;
        psH += d2 * av0 + d3 * av1;
        qdL += d0 * dv0 + d1 * dv1;
        qdH += d2 * dv0 + d3 * dv1;
        if (rowLo < n) {
            __half2 hlo = __floats2half2_rn(d0, d1);
            *(__half2*)&hh_out[(size_t)rowLo * D + col] = hlo;
        }
        if (rowHi < n) {
            __half2 hhi = __floats2half2_rn(d2, d3);
            *(__half2*)&hh_out[(size_t)rowHi * D + col] = hhi;
        }
    }

    psL += __shfl_xor_sync(0xffffffffu, psL, 1);
    psL += __shfl_xor_sync(0xffffffffu, psL, 2);
    psH += __shfl_xor_sync(0xffffffffu, psH, 1);
    psH += __shfl_xor_sync(0xffffffffu, psH, 2);
    qdL += __shfl_xor_sync(0xffffffffu, qdL, 1);
    qdL += __shfl_xor_sync(0xffffffffu, qdL, 2);
    qdH += __shfl_xor_sync(0xffffffffu, qdH, 1);
    qdH += __shfl_xor_sync(0xffffffffu, qdH, 2);
    if ((lane & 3) == 0) {
        if (rowLo < n) { g_ssrc[rowLo] = psL; g_sdst[rowLo] = qdL; }
        if (rowHi < n) { g_ssrc[rowHi] = psH; g_sdst[rowHi] = qdH; }
    }
}

// ---------------------------------------------------------------- HMMA GEMM (layer 2)
__global__ void __launch_bounds__(128) hmma_gemm_kernel(
    const float* __restrict__ X, const __half* __restrict__ W16,
    __half* __restrict__ hh_out,
    const float* __restrict__ asrc, const float* __restrict__ adst, int n) {
    extern __shared__ __half smh[];
    __half* Xs = smh;
    __half* Ws = smh + 64 * XPAD;
    int tid = threadIdx.x;
    int lane = tid & 31;
    int warp = tid >> 5;
    int rowbase = blockIdx.x * 64;

    for (int i = tid; i < D * D; i += 128)
        Ws[(i >> 7) * XPAD + (i & 127)] = W16[i];
    for (int i = tid; i < 64 * D; i += 128) {
        int r = rowbase + (i >> 7);
        Xs[(i >> 7) * XPAD + (i & 127)] =
            (r < n) ? __float2half_rn(X[(size_t)r * D + (i & 127)]) : __half(0.f);
    }
    __syncthreads();

    unsigned xs_base = (unsigned)__cvta_generic_to_shared(Xs);
    unsigned ws_base = (unsigned)__cvta_generic_to_shared(Ws);
    int warpRow = warp * 16;

    unsigned a[8][4];
#pragma unroll
    for (int ka = 0; ka < 8; ka++) {
        unsigned addr = xs_base +
            ((warpRow + (lane & 15)) * XPAD + ka * 16 + (lane >> 4) * 8) * 2;
        asm volatile("ldmatrix.sync.aligned.m8n8.x4.shared.b16 {%0,%1,%2,%3}, [%4];"
                     : "=r"(a[ka][0]), "=r"(a[ka][1]), "=r"(a[ka][2]), "=r"(a[ka][3])
                     : "r"(addr));
    }

    int g = lane >> 2;
    int c2 = (lane & 3) * 2;
    int rowLo = rowbase + warpRow + g;
    int rowHi = rowLo + 8;

    float psL = 0.f, psH = 0.f, qdL = 0.f, qdH = 0.f;

#pragma unroll
    for (int j = 0; j < 16; j++) {
        float d0 = 0.f, d1 = 0.f, d2 = 0.f, d3 = 0.f;
#pragma unroll
        for (int ka = 0; ka < 8; ka++) {
            unsigned b0, b1;
            unsigned baddr = ws_base + ((ka * 16 + (lane & 15)) * XPAD + j * 8) * 2;
            asm volatile("ldmatrix.sync.aligned.m8n8.x2.trans.shared.b16 {%0,%1}, [%2];"
                         : "=r"(b0), "=r"(b1) : "r"(baddr));
            asm volatile(
                "mma.sync.aligned.m16n8k16.row.col.f32.f16.f16.f32 "
                "{%0,%1,%2,%3}, {%4,%5,%6,%7}, {%8,%9}, {%0,%1,%2,%3};"
                : "+f"(d0), "+f"(d1), "+f"(d2), "+f"(d3)
                : "r"(a[ka][0]), "r"(a[ka][1]), "r"(a[ka][2]), "r"(a[ka][3]),
                  "r"(b0), "r"(b1));
        }
        int col = j * 8 + c2;
        float av0 = asrc[col], av1 = asrc[col + 1];
        float dv0 = adst[col], dv1 = adst[col + 1];
        psL += d0 * av0 + d1 * av1;
        psH += d2 * av0 + d3 * av1;
        qdL += d0 * dv0 + d1 * dv1;
        qdH += d2 * dv0 + d3 * dv1;
        if (rowLo < n) {
            __half2 hlo = __floats2half2_rn(d0, d1);
            *(__half2*)&hh_out[(size_t)rowLo * D + col] = hlo;
        }
        if (rowHi < n) {
            __half2 hhi = __floats2half2_rn(d2, d3);
            *(__half2*)&hh_out[(size_t)rowHi * D + col] = hhi;
        }
    }

    psL += __shfl_xor_sync(0xffffffffu, psL, 1);
    psL += __shfl_xor_sync(0xffffffffu, psL, 2);
    psH += __shfl_xor_sync(0xffffffffu, psH, 1);
    psH += __shfl_xor_sync(0xffffffffu, psH, 2);
    qdL += __shfl_xor_sync(0xffffffffu, qdL, 1);
    qdL += __shfl_xor_sync(0xffffffffu, qdL, 2);
    qdH += __shfl_xor_sync(0xffffffffu, qdH, 1);
    qdH += __shfl_xor_sync(0xffffffffu, qdH, 2);
    if ((lane & 3) == 0) {
        if (rowLo < n) { g_ssrc[rowLo] = psL; g_sdst[rowLo] = qdL; }
        if (rowHi < n) { g_ssrc[rowHi] = psH; g_sdst[rowHi] = qdH; }
    }
}

// ---------------------------------------------------------------- HMMA output GEMM (+ counter reset)
#define WPAD 72
__global__ void __launch_bounds__(128) hmma_out_kernel(
    const float* __restrict__ X, const __half* __restrict__ Wo16,
    const float* __restrict__ bias, float* __restrict__ Y, int n) {
    extern __shared__ __half smh[];
    __half* Xs = smh;
    __half* Ws = smh + 64 * XPAD;
    int tid = threadIdx.x;
    int lane = tid & 31;
    int warp = tid >> 5;
    int rowbase = blockIdx.x * 64;

    // reset rank/scan counters for the next replay
    if (blockIdx.x == 0 && tid == 0) {
        g_cnt = 0;
        g_cnt_rank = 0;
    }

    for (int i = tid; i < D * DOUT; i += 128)
        Ws[(i / DOUT) * WPAD + (i % DOUT)] = Wo16[i];
    for (int i = tid; i < 64 * D; i += 128) {
        int r = rowbase + (i >> 7);
        Xs[(i >> 7) * XPAD + (i & 127)] =
            (r < n) ? __float2half_rn(X[(size_t)r * D + (i & 127)]) : __half(0.f);
    }
    __syncthreads();

    unsigned xs_base = (unsigned)__cvta_generic_to_shared(Xs);
    unsigned ws_base = (unsigned)__cvta_generic_to_shared(Ws);
    int warpRow = warp * 16;

    unsigned a[8][4];
#pragma unroll
    for (int ka = 0; ka < 8; ka++) {
        unsigned addr = xs_base +
            ((warpRow + (lane & 15)) * XPAD + ka * 16 + (lane >> 4) * 8) * 2;
        asm volatile("ldmatrix.sync.aligned.m8n8.x4.shared.b16 {%0,%1,%2,%3}, [%4];"
                     : "=r"(a[ka][0]), "=r"(a[ka][1]), "=r"(a[ka][2]), "=r"(a[ka][3])
                     : "r"(addr));
    }

    int g = lane >> 2;
    int c2 = (lane & 3) * 2;
    int rowLo = rowbase + warpRow + g;
    int rowHi = rowLo + 8;

#pragma unroll
    for (int j = 0; j < 8; j++) {
        float d0 = 0.f, d1 = 0.f, d2 = 0.f, d3 = 0.f;
#pragma unroll
        for (int ka = 0; ka < 8; ka++) {
            unsigned b0, b1;
            unsigned baddr = ws_base + ((ka * 16 + (lane & 15)) * WPAD + j * 8) * 2;
            asm volatile("ldmatrix.sync.aligned.m8n8.x2.trans.shared.b16 {%0,%1}, [%2];"
                         : "=r"(b0), "=r"(b1) : "r"(baddr));
            asm volatile(
                "mma.sync.aligned.m16n8k16.row.col.f32.f16.f16.f32 "
                "{%0,%1,%2,%3}, {%4,%5,%6,%7}, {%8,%9}, {%0,%1,%2,%3};"
                : "+f"(d0), "+f"(d1), "+f"(d2), "+f"(d3)
                : "r"(a[ka][0]), "r"(a[ka][1]), "r"(a[ka][2]), "r"(a[ka][3]),
                  "r"(b0), "r"(b1));
        }
        int col = j * 8 + c2;
        float bb0 = bias[col], bb1 = bias[col + 1];
        if (rowLo < n) {
            float2 o = make_float2(d0 + bb0, d1 + bb1);
            *(float2*)&Y[(size_t)rowLo * DOUT + col] = o;
        }
        if (rowHi < n) {
            float2 o = make_float2(d2 + bb0, d3 + bb1);
            *(float2*)&Y[(size_t)rowHi * DOUT + col] = o;
        }
    }
}

// ---------------------------------------------------------------- fused alpha + aggregation
// One warp per destination node, edge-pair consumption (16 lanes per edge).
// __launch_bounds__(256, 6) caps regs (~42) for 6 blocks/SM occupancy.
#define CH 64
__global__ void __launch_bounds__(256, 6) gat_edge_kernel(
    const __half* __restrict__ hh, const float* __restrict__ bias,
    float* __restrict__ out, int n, int do_relu) {
    __shared__ float2 stage[8][CH];
    int gt = blockIdx.x * blockDim.x + threadIdx.x;
    int node = gt >> 5, lane = gt & 31;
    int wslot = (threadIdx.x >> 5);
    if (node >= n) return;

    int beg = g_offs[node];
    int end = g_offs[node + 1];
    float sd = g_sdst[node];
    int h = lane >> 4;            // half-warp: which edge of the pair
    int lane8 = lane & 15;        // feature subgroup (8 halves)
    const char* hbase = (const char*)hh + lane8 * 16;

    float denom = 0.f;
    unsigned long long acc0 = 0ull, acc1 = 0ull, acc2 = 0ull, acc3 = 0ull;

    for (int cb = beg; cb < end; cb += CH) {
        int m = min(CH, end - cb);
        for (int t = lane; t < m; t += 32) {
            int s = g_esrc[cb + t];
            float ex = __expf(fmaxf(g_ssrc[s] + sd, 0.f));
            denom += ex;
            stage[wslot][t] = make_float2(__int_as_float(s << 8), ex);  // byte offset
        }
        if ((m & 1) && lane == 0)
            stage[wslot][m] = make_float2(stage[wslot][0].x, 0.f);
        __syncwarp();

        int mp = (m + 1) & ~1;
        int k = 0;
        for (; k + 8 <= mp; k += 8) {
            float2 p0 = stage[wslot][k + 0 + h];
            float2 p1 = stage[wslot][k + 2 + h];
            float2 p2 = stage[wslot][k + 4 + h];
            float2 p3 = stage[wslot][k + 6 + h];
            uint4 v0 = *(const uint4*)(hbase + (unsigned)__float_as_int(p0.x));
            uint4 v1 = *(const uint4*)(hbase + (unsigned)__float_as_int(p1.x));
            uint4 v2 = *(const uint4*)(hbase + (unsigned)__float_as_int(p2.x));
            uint4 v3 = *(const uint4*)(hbase + (unsigned)__float_as_int(p3.x));
#define EDGE_STEP(vv, ww) do { \
                unsigned long long w_ = dup2(ww); \
                float2 a0_ = __half22float2(*(__half2*)&(vv).x); \
                float2 a1_ = __half22float2(*(__half2*)&(vv).y); \
                float2 a2_ = __half22float2(*(__half2*)&(vv).z); \
                float2 a3_ = __half22float2(*(__half2*)&(vv).w); \
                ffma2(acc0, w_, *(unsigned long long*)&a0_); \
                ffma2(acc1, w_, *(unsigned long long*)&a1_); \
                ffma2(acc2, w_, *(unsigned long long*)&a2_); \
                ffma2(acc3, w_, *(unsigned long long*)&a3_); \
            } while (0)
            EDGE_STEP(v0, p0.y);
            EDGE_STEP(v1, p1.y);
            EDGE_STEP(v2, p2.y);
            EDGE_STEP(v3, p3.y);
        }
        for (; k < mp; k += 2) {
            float2 p = stage[wslot][k + h];
            uint4 v = *(const uint4*)(hbase + (unsigned)__float_as_int(p.x));
            EDGE_STEP(v, p.y);
        }
#undef EDGE_STEP
        __syncwarp();
    }

#pragma unroll
    for (int o = 16; o; o >>= 1) denom += __shfl_xor_sync(0xffffffffu, denom, o);
    float inv = 1.f / denom;

    float2 f0 = *(float2*)&acc0;
    float2 f1 = *(float2*)&acc1;
    float2 f2 = *(float2*)&acc2;
    float2 f3 = *(float2*)&acc3;
    f0.x += __shfl_xor_sync(0xffffffffu, f0.x, 16);
    f0.y += __shfl_xor_sync(0xffffffffu, f0.y, 16);
    f1.x += __shfl_xor_sync(0xffffffffu, f1.x, 16);
    f1.y += __shfl_xor_sync(0xffffffffu, f1.y, 16);
    f2.x += __shfl_xor_sync(0xffffffffu, f2.x, 16);
    f2.y += __shfl_xor_sync(0xffffffffu, f2.y, 16);
    f3.x += __shfl_xor_sync(0xffffffffu, f3.x, 16);
    f3.y += __shfl_xor_sync(0xffffffffu, f3.y, 16);

    if (h == 0) {
        int fb = lane8 * 8;
        float4 b0 = *(const float4*)&bias[fb];
        float4 b1 = *(const float4*)&bias[fb + 4];
        float4 o0, o1;
        o0.x = f0.x * inv + b0.x;
        o0.y = f0.y * inv + b0.y;
        o0.z = f1.x * inv + b0.z;
        o0.w = f1.y * inv + b0.w;
        o1.x = f2.x * inv + b1.x;
        o1.y = f2.y * inv + b1.y;
        o1.z = f3.x * inv + b1.z;
        o1.w = f3.y * inv + b1.w;
        if (do_relu) {
            o0.x = fmaxf(o0.x, 0.f); o0.y = fmaxf(o0.y, 0.f);
            o0.z = fmaxf(o0.z, 0.f); o0.w = fmaxf(o0.w, 0.f);
            o1.x = fmaxf(o1.x, 0.f); o1.y = fmaxf(o1.y, 0.f);
            o1.z = fmaxf(o1.z, 0.f); o1.w = fmaxf(o1.w, 0.f);
        }
        *(float4*)&out[(size_t)node * D + fb] = o0;
        *(float4*)&out[(size_t)node * D + fb + 4] = o1;
    }
}

// ---------------------------------------------------------------- launch
extern "C" void kernel_launch(void* const* d_in, const int* in_sizes, int n_in,
                              void* d_out, int out_size) {
    const float* node_x = (const float*)d_in[0];
    const int*   ei     = (const int*)d_in[1];
    const float* W1     = (const float*)d_in[2];
    const float* as1    = (const float*)d_in[3];
    const float* ad1    = (const float*)d_in[4];
    const float* b1     = (const float*)d_in[5];
    const float* W2     = (const float*)d_in[6];
    const float* as2    = (const float*)d_in[7];
    const float* ad2    = (const float*)d_in[8];
    const float* b2     = (const float*)d_in[9];
    const float* Wout   = (const float*)d_in[10];
    const float* bout   = (const float*)d_in[11];
    float* out = (float*)d_out;

    int n = in_sizes[0] / D;       // 50000
    int E = in_sizes[1] / 2;       // 1600000

    float* x_ptr;
    __half *hh_ptr, *w16a_ptr, *w16b_ptr, *w16o_ptr;
    cudaGetSymbolAddress((void**)&x_ptr, g_x);
    cudaGetSymbolAddress((void**)&hh_ptr, g_hh);
    cudaGetSymbolAddress((void**)&w16a_ptr, g_w16a);
    cudaGetSymbolAddress((void**)&w16b_ptr, g_w16b);
    cudaGetSymbolAddress((void**)&w16o_ptr, g_w16o);

    const int SMEM_HMMA = (64 * XPAD + 128 * XPAD) * (int)sizeof(__half); // ~51 KB
    const int SMEM_OUT  = (64 * XPAD + 128 * WPAD) * (int)sizeof(__half); // ~35 KB
    cudaFuncSetAttribute(hmma_gemm_place_kernel, cudaFuncAttributeMaxDynamicSharedMemorySize, SMEM_HMMA);
    cudaFuncSetAttribute(hmma_gemm_kernel, cudaFuncAttributeMaxDynamicSharedMemorySize, SMEM_HMMA);
    cudaFuncSetAttribute(hmma_out_kernel, cudaFuncAttributeMaxDynamicSharedMemorySize, SMEM_OUT);

    int tot = E + n;
    int nb = (n + SCAN_B - 1) / SCAN_B;
    int RB = (tot + 1023) / 1024;
    int agg_grid = (n * 32 + 255) / 256;
    int hmma_grid = (n + 63) / 64;
    int place_blocks = (tot + 128 * PLACE_EPT - 1) / (128 * PLACE_EPT);

    // CSR rank + W conversion + scan, all in one launch
    rank_scan_kernel<<<CONV_BLOCKS + RB + nb, 256>>>(ei, E, n, W1, W2, Wout, RB, nb, tot);

    // layer-1 GEMM + placement merged
    hmma_gemm_place_kernel<<<hmma_grid + place_blocks, 128, SMEM_HMMA>>>(
        node_x, w16a_ptr, hh_ptr, as1, ad1, n, ei, E, hmma_grid);
    gat_edge_kernel<<<agg_grid, 256>>>(hh_ptr, b1, x_ptr, n, 1);

    // layer 2
    hmma_gemm_kernel<<<hmma_grid, 128, SMEM_HMMA>>>(x_ptr, w16b_ptr, hh_ptr, as2, ad2, n);
    gat_edge_kernel<<<agg_grid, 256>>>(hh_ptr, b2, x_ptr, n, 0);

    // output linear (HMMA) + counter reset for next replay
    hmma_out_kernel<<<hmma_grid, 128, SMEM_OUT>>>(x_ptr, w16o_ptr, bout, out, n);
}

// round 13
// speedup vs baseline: 2.0482x; 1.1759x over previous
#include <cuda_runtime.h>
#include <cuda_fp16.h>

// Problem shape (fixed per dataset)
#define NN   50000
#define EE_CAP 1650512   // E + N self loops, with margin
#define D    128
#define DOUT 64
#define SCAN_B 256
#define CONV_BLOCKS 96   // 64 blocks W1/W2 + 32 blocks Wout

// ---- device scratch (no allocation allowed) ----
__device__ __half g_hh[NN * D];     // fp16 transformed features for the edge gather
__device__ float  g_x[NN * D];      // aggregation output / next layer input
__device__ float  g_ssrc[NN];       // h @ att_src
__device__ float  g_sdst[NN];       // h @ att_dst
__device__ __half g_w16a[D * D];    // W1 in fp16
__device__ __half g_w16b[D * D];    // W2 in fp16
__device__ __half g_w16o[D * DOUT]; // W_out in fp16
__device__ int    g_deg[NN];        // zeroed at static init; re-zeroed by scan portion
__device__ int    g_offs[NN + 1];
__device__ int    g_bsum[(NN + SCAN_B - 1) / SCAN_B];
__device__ int    g_cnt;            // scan publish counter  (reset by hmma_out)
__device__ int    g_cnt_rank;       // rank completion counter (reset by hmma_out)
__device__ int    g_rank[EE_CAP];   // per edge: (rank << 16) | dst
__device__ int    g_esrc[EE_CAP];   // CSR-by-dst: source node per edge

// packed f32x2 fma helpers
__device__ __forceinline__ void ffma2(unsigned long long& acc,
                                      unsigned long long a,
                                      unsigned long long b) {
    asm("fma.rn.f32x2 %0, %1, %2, %0;" : "+l"(acc) : "l"(a), "l"(b));
}
__device__ __forceinline__ unsigned long long dup2(float v) {
    unsigned long long r;
    asm("mov.b64 %0, {%1, %1};" : "=l"(r) : "f"(v));
    return r;
}

// ---------------------------------------------------------------- rank + W convert + scan (one launch)
__global__ void rank_scan_kernel(const int* __restrict__ ei, int E, int n,
                                 const float* __restrict__ W1f,
                                 const float* __restrict__ W2f,
                                 const float* __restrict__ Wof,
                                 int RB, int nb, int total) {
    if (blockIdx.x < 64) {
        int i = blockIdx.x * 256 + threadIdx.x;
        g_w16a[i] = __float2half_rn(W1f[i]);
        g_w16b[i] = __float2half_rn(W2f[i]);
        return;
    }
    if (blockIdx.x < CONV_BLOCKS) {
        int i = (blockIdx.x - 64) * 256 + threadIdx.x;
        if (i < D * DOUT) g_w16o[i] = __float2half_rn(Wof[i]);
        return;
    }
    if ((int)blockIdx.x < CONV_BLOCKS + RB) {
        // ---- rank portion ----
        int i0 = (((int)blockIdx.x - CONV_BLOCKS) * 256 + threadIdx.x) * 4;
        if (i0 + 3 < E && (E & 3) == 0) {
            int4 d4 = *(const int4*)&ei[E + i0];
            int4 r4;
            r4.x = (atomicAdd(&g_deg[d4.x], 1) << 16) | d4.x;
            r4.y = (atomicAdd(&g_deg[d4.y], 1) << 16) | d4.y;
            r4.z = (atomicAdd(&g_deg[d4.z], 1) << 16) | d4.z;
            r4.w = (atomicAdd(&g_deg[d4.w], 1) << 16) | d4.w;
            *(int4*)&g_rank[i0] = r4;
        } else {
#pragma unroll
            for (int u = 0; u < 4; u++) {
                int i = i0 + u;
                if (i < E) {
                    int d = ei[E + i];
                    g_rank[i] = (atomicAdd(&g_deg[d], 1) << 16) | d;
                } else if (i < E + n) {
                    int v = i - E;
                    g_rank[i] = (atomicAdd(&g_deg[v], 1) << 16) | v;
                }
            }
        }
        __syncthreads();
        if (threadIdx.x == 0) {
            __threadfence();
            atomicAdd(&g_cnt_rank, 1);
        }
        return;
    }

    // ---- scan portion ----
    __shared__ int ws[SCAN_B / 32];
    __shared__ int s_part;
    int sb = (int)blockIdx.x - CONV_BLOCKS - RB;
    int tid = threadIdx.x;
    int lane = tid & 31, wid = tid >> 5;

    if (tid == 0) {
        while (*(volatile int*)&g_cnt_rank < RB) { }
    }
    __syncthreads();
    __threadfence();

    int i = sb * SCAN_B + tid;
    int v = 0;
    if (i < n) {
        v = g_deg[i];
        g_deg[i] = 0;
    }
    int x = v;
#pragma unroll
    for (int o = 1; o < 32; o <<= 1) {
        int y = __shfl_up_sync(0xffffffffu, x, o);
        if (lane >= o) x += y;
    }
    if (lane == 31) ws[wid] = x;
    __syncthreads();
    int base = 0;
#pragma unroll
    for (int w = 0; w < SCAN_B / 32; w++)
        if (w < wid) base += ws[w];
    int ex = base + x - v;

    if (tid == SCAN_B - 1) {
        g_bsum[sb] = ex + v;
        __threadfence();
        atomicAdd(&g_cnt, 1);
    }
    if (tid == 0) {
        while (*(volatile int*)&g_cnt < nb) { }
    }
    __syncthreads();

    int part = 0;
    if (tid < sb) part = __ldcg(&g_bsum[tid]);
#pragma unroll
    for (int o = 16; o; o >>= 1) part += __shfl_xor_sync(0xffffffffu, part, o);
    if (lane == 0) ws[wid] = part;
    __syncthreads();
    if (tid == 0) {
        int p = 0;
#pragma unroll
        for (int w = 0; w < SCAN_B / 32; w++) p += ws[w];
        s_part = p;
    }
    __syncthreads();

    if (i < n) g_offs[i] = ex + s_part;
    if (i == 0) g_offs[n] = total;
}

// ---------------------------------------------------------------- HMMA GEMM core (GAT layers)
// 256 threads / 8 warps / 128 rows per block. Warp = 16 rows, all 128 cols.
// B loads use ldmatrix.x4.trans: one load covers both k-halves of TWO j-tiles
// (lanes 0-15 -> cols j2*16, lanes 16-31 -> cols j2*16+8) => half the LDSM
// count and two independent MMA chains per load.
#define XPAD 136
__device__ __forceinline__ void hmma_gemm_body(
    const float* __restrict__ X, const __half* __restrict__ W16,
    __half* __restrict__ hh_out,
    const float* __restrict__ asrc, const float* __restrict__ adst, int n,
    int rowbase, __half* smh) {
    __half* Xs = smh;                 // 128 x XPAD
    __half* Ws = smh + 128 * XPAD;    // 128 x XPAD
    int tid = threadIdx.x;
    int lane = tid & 31;
    int warp = tid >> 5;              // 0..7

    for (int i = tid; i < D * D; i += 256)
        Ws[(i >> 7) * XPAD + (i & 127)] = W16[i];
    for (int i = tid; i < 128 * D; i += 256) {
        int r = rowbase + (i >> 7);
        Xs[(i >> 7) * XPAD + (i & 127)] =
            (r < n) ? __float2half_rn(X[(size_t)r * D + (i & 127)]) : __half(0.f);
    }
    __syncthreads();

    unsigned xs_base = (unsigned)__cvta_generic_to_shared(Xs);
    unsigned ws_base = (unsigned)__cvta_generic_to_shared(Ws);
    int warpRow = warp * 16;

    unsigned a[8][4];
#pragma unroll
    for (int ka = 0; ka < 8; ka++) {
        unsigned addr = xs_base +
            ((warpRow + (lane & 15)) * XPAD + ka * 16 + (lane >> 4) * 8) * 2;
        asm volatile("ldmatrix.sync.aligned.m8n8.x4.shared.b16 {%0,%1,%2,%3}, [%4];"
                     : "=r"(a[ka][0]), "=r"(a[ka][1]), "=r"(a[ka][2]), "=r"(a[ka][3])
                     : "r"(addr));
    }

    int g = lane >> 2;
    int c2 = (lane & 3) * 2;
    int rowLo = rowbase + warpRow + g;
    int rowHi = rowLo + 8;

    float psL = 0.f, psH = 0.f, qdL = 0.f, qdH = 0.f;

#pragma unroll
    for (int j2 = 0; j2 < 8; j2++) {
        float d0 = 0.f, d1 = 0.f, d2 = 0.f, d3 = 0.f;   // j-tile A
        float e0 = 0.f, e1 = 0.f, e2 = 0.f, e3 = 0.f;   // j-tile B
#pragma unroll
        for (int ka = 0; ka < 8; ka++) {
            unsigned b0, b1, b2, b3;
            unsigned baddr = ws_base +
                ((ka * 16 + (lane & 15)) * XPAD + j2 * 16 + (lane >> 4) * 8) * 2;
            asm volatile("ldmatrix.sync.aligned.m8n8.x4.trans.shared.b16 {%0,%1,%2,%3}, [%4];"
                         : "=r"(b0), "=r"(b1), "=r"(b2), "=r"(b3) : "r"(baddr));
            asm volatile(
                "mma.sync.aligned.m16n8k16.row.col.f32.f16.f16.f32 "
                "{%0,%1,%2,%3}, {%4,%5,%6,%7}, {%8,%9}, {%0,%1,%2,%3};"
                : "+f"(d0), "+f"(d1), "+f"(d2), "+f"(d3)
                : "r"(a[ka][0]), "r"(a[ka][1]), "r"(a[ka][2]), "r"(a[ka][3]),
                  "r"(b0), "r"(b1));
            asm volatile(
                "mma.sync.aligned.m16n8k16.row.col.f32.f16.f16.f32 "
                "{%0,%1,%2,%3}, {%4,%5,%6,%7}, {%8,%9}, {%0,%1,%2,%3};"
                : "+f"(e0), "+f"(e1), "+f"(e2), "+f"(e3)
                : "r"(a[ka][0]), "r"(a[ka][1]), "r"(a[ka][2]), "r"(a[ka][3]),
                  "r"(b2), "r"(b3));
        }
        int colA = j2 * 16 + c2;
        int colB = colA + 8;
        float avA0 = asrc[colA], avA1 = asrc[colA + 1];
        float dvA0 = adst[colA], dvA1 = adst[colA + 1];
        float avB0 = asrc[colB], avB1 = asrc[colB + 1];
        float dvB0 = adst[colB], dvB1 = adst[colB + 1];
        psL += d0 * avA0 + d1 * avA1 + e0 * avB0 + e1 * avB1;
        psH += d2 * avA0 + d3 * avA1 + e2 * avB0 + e3 * avB1;
        qdL += d0 * dvA0 + d1 * dvA1 + e0 * dvB0 + e1 * dvB1;
        qdH += d2 * dvA0 + d3 * dvA1 + e2 * dvB0 + e3 * dvB1;
        if (rowLo < n) {
            __half2 hA = __floats2half2_rn(d0, d1);
            __half2 hB = __floats2half2_rn(e0, e1);
            *(__half2*)&hh_out[(size_t)rowLo * D + colA] = hA;
            *(__half2*)&hh_out[(size_t)rowLo * D + colB] = hB;
        }
        if (rowHi < n) {
            __half2 hA = __floats2half2_rn(d2, d3);
            __half2 hB = __floats2half2_rn(e2, e3);
            *(__half2*)&hh_out[(size_t)rowHi * D + colA] = hA;
            *(__half2*)&hh_out[(size_t)rowHi * D + colB] = hB;
        }
    }

    psL += __shfl_xor_sync(0xffffffffu, psL, 1);
    psL += __shfl_xor_sync(0xffffffffu, psL, 2);
    psH += __shfl_xor_sync(0xffffffffu, psH, 1);
    psH += __shfl_xor_sync(0xffffffffu, psH, 2);
    qdL += __shfl_xor_sync(0xffffffffu, qdL, 1);
    qdL += __shfl_xor_sync(0xffffffffu, qdL, 2);
    qdH += __shfl_xor_sync(0xffffffffu, qdH, 1);
    qdH += __shfl_xor_sync(0xffffffffu, qdH, 2);
    if ((lane & 3) == 0) {
        if (rowLo < n) { g_ssrc[rowLo] = psL; g_sdst[rowLo] = qdL; }
        if (rowHi < n) { g_ssrc[rowHi] = psH; g_sdst[rowHi] = qdH; }
    }
}

// ---- layer-1: GEMM blocks + placement blocks in one launch ----
#define PLACE_EPT 4
__global__ void __launch_bounds__(256) hmma_gemm_place_kernel(
    const float* __restrict__ X, const __half* __restrict__ W16,
    __half* __restrict__ hh_out,
    const float* __restrict__ asrc, const float* __restrict__ adst, int n,
    const int* __restrict__ ei, int E, int hmma_grid) {
    if ((int)blockIdx.x >= hmma_grid) {
        int pb = (int)blockIdx.x - hmma_grid;
        int i0 = (pb * 256 + (int)threadIdx.x) * PLACE_EPT;
#pragma unroll
        for (int q = 0; q < PLACE_EPT; q += 4) {
            int ib = i0 + q;
            if (ib + 3 < E && (E & 3) == 0) {
                int4 s4 = *(const int4*)&ei[ib];
                int4 r4 = *(const int4*)&g_rank[ib];
                g_esrc[g_offs[r4.x & 0xFFFF] + (r4.x >> 16)] = s4.x;
                g_esrc[g_offs[r4.y & 0xFFFF] + (r4.y >> 16)] = s4.y;
                g_esrc[g_offs[r4.z & 0xFFFF] + (r4.z >> 16)] = s4.z;
                g_esrc[g_offs[r4.w & 0xFFFF] + (r4.w >> 16)] = s4.w;
            } else {
#pragma unroll
                for (int u = 0; u < 4; u++) {
                    int i = ib + u;
                    if (i < E) {
                        int pk = g_rank[i];
                        g_esrc[g_offs[pk & 0xFFFF] + (pk >> 16)] = ei[i];
                    } else if (i < E + n) {
                        int pk = g_rank[i];
                        g_esrc[g_offs[pk & 0xFFFF] + (pk >> 16)] = i - E;
                    }
                }
            }
        }
        return;
    }
    extern __shared__ __half smh[];
    hmma_gemm_body(X, W16, hh_out, asrc, adst, n, blockIdx.x * 128, smh);
}

__global__ void __launch_bounds__(256) hmma_gemm_kernel(
    const float* __restrict__ X, const __half* __restrict__ W16,
    __half* __restrict__ hh_out,
    const float* __restrict__ asrc, const float* __restrict__ adst, int n) {
    extern __shared__ __half smh[];
    hmma_gemm_body(X, W16, hh_out, asrc, adst, n, blockIdx.x * 128, smh);
}

// ---------------------------------------------------------------- HMMA output GEMM (+ counter reset)
// 128 threads / 64 rows / x4.trans B loads over 4 j2-tiles.
#define WPAD 72
__global__ void __launch_bounds__(128) hmma_out_kernel(
    const float* __restrict__ X, const __half* __restrict__ Wo16,
    const float* __restrict__ bias, float* __restrict__ Y, int n) {
    extern __shared__ __half smh[];
    __half* Xs = smh;                 // 64 x XPAD
    __half* Ws = smh + 64 * XPAD;     // 128 x WPAD
    int tid = threadIdx.x;
    int lane = tid & 31;
    int warp = tid >> 5;
    int rowbase = blockIdx.x * 64;

    if (blockIdx.x == 0 && tid == 0) {
        g_cnt = 0;
        g_cnt_rank = 0;
    }

    for (int i = tid; i < D * DOUT; i += 128)
        Ws[(i / DOUT) * WPAD + (i % DOUT)] = Wo16[i];
    for (int i = tid; i < 64 * D; i += 128) {
        int r = rowbase + (i >> 7);
        Xs[(i >> 7) * XPAD + (i & 127)] =
            (r < n) ? __float2half_rn(X[(size_t)r * D + (i & 127)]) : __half(0.f);
    }
    __syncthreads();

    unsigned xs_base = (unsigned)__cvta_generic_to_shared(Xs);
    unsigned ws_base = (unsigned)__cvta_generic_to_shared(Ws);
    int warpRow = warp * 16;

    unsigned a[8][4];
#pragma unroll
    for (int ka = 0; ka < 8; ka++) {
        unsigned addr = xs_base +
            ((warpRow + (lane & 15)) * XPAD + ka * 16 + (lane >> 4) * 8) * 2;
        asm volatile("ldmatrix.sync.aligned.m8n8.x4.shared.b16 {%0,%1,%2,%3}, [%4];"
                     : "=r"(a[ka][0]), "=r"(a[ka][1]), "=r"(a[ka][2]), "=r"(a[ka][3])
                     : "r"(addr));
    }

    int g = lane >> 2;
    int c2 = (lane & 3) * 2;
    int rowLo = rowbase + warpRow + g;
    int rowHi = rowLo + 8;

#pragma unroll
    for (int j2 = 0; j2 < 4; j2++) {
        float d0 = 0.f, d1 = 0.f, d2 = 0.f, d3 = 0.f;
        float e0 = 0.f, e1 = 0.f, e2 = 0.f, e3 = 0.f;
#pragma unroll
        for (int ka = 0; ka < 8; ka++) {
            unsigned b0, b1, b2, b3;
            unsigned baddr = ws_base +
                ((ka * 16 + (lane & 15)) * WPAD + j2 * 16 + (lane >> 4) * 8) * 2;
            asm volatile("ldmatrix.sync.aligned.m8n8.x4.trans.shared.b16 {%0,%1,%2,%3}, [%4];"
                         : "=r"(b0), "=r"(b1), "=r"(b2), "=r"(b3) : "r"(baddr));
            asm volatile(
                "mma.sync.aligned.m16n8k16.row.col.f32.f16.f16.f32 "
                "{%0,%1,%2,%3}, {%4,%5,%6,%7}, {%8,%9}, {%0,%1,%2,%3};"
                : "+f"(d0), "+f"(d1), "+f"(d2), "+f"(d3)
                : "r"(a[ka][0]), "r"(a[ka][1]), "r"(a[ka][2]), "r"(a[ka][3]),
                  "r"(b0), "r"(b1));
            asm volatile(
                "mma.sync.aligned.m16n8k16.row.col.f32.f16.f16.f32 "
                "{%0,%1,%2,%3}, {%4,%5,%6,%7}, {%8,%9}, {%0,%1,%2,%3};"
                : "+f"(e0), "+f"(e1), "+f"(e2), "+f"(e3)
                : "r"(a[ka][0]), "r"(a[ka][1]), "r"(a[ka][2]), "r"(a[ka][3]),
                  "r"(b2), "r"(b3));
        }
        int colA = j2 * 16 + c2;
        int colB = colA + 8;
        float bA0 = bias[colA], bA1 = bias[colA + 1];
        float bB0 = bias[colB], bB1 = bias[colB + 1];
        if (rowLo < n) {
            *(float2*)&Y[(size_t)rowLo * DOUT + colA] = make_float2(d0 + bA0, d1 + bA1);
            *(float2*)&Y[(size_t)rowLo * DOUT + colB] = make_float2(e0 + bB0, e1 + bB1);
        }
        if (rowHi < n) {
            *(float2*)&Y[(size_t)rowHi * DOUT + colA] = make_float2(d2 + bA0, d3 + bA1);
            *(float2*)&Y[(size_t)rowHi * DOUT + colB] = make_float2(e2 + bB0, e3 + bB1);
        }
    }
}

// ---------------------------------------------------------------- fused alpha + aggregation
#define CH 64
__global__ void __launch_bounds__(256, 6) gat_edge_kernel(
    const __half* __restrict__ hh, const float* __restrict__ bias,
    float* __restrict__ out, int n, int do_relu) {
    __shared__ float2 stage[8][CH];
    int gt = blockIdx.x * blockDim.x + threadIdx.x;
    int node = gt >> 5, lane = gt & 31;
    int wslot = (threadIdx.x >> 5);
    if (node >= n) return;

    int beg = g_offs[node];
    int end = g_offs[node + 1];
    float sd = g_sdst[node];
    int h = lane >> 4;
    int lane8 = lane & 15;
    const char* hbase = (const char*)hh + lane8 * 16;

    float denom = 0.f;
    unsigned long long acc0 = 0ull, acc1 = 0ull, acc2 = 0ull, acc3 = 0ull;

    for (int cb = beg; cb < end; cb += CH) {
        int m = min(CH, end - cb);
        for (int t = lane; t < m; t += 32) {
            int s = g_esrc[cb + t];
            float ex = __expf(fmaxf(g_ssrc[s] + sd, 0.f));
            denom += ex;
            stage[wslot][t] = make_float2(__int_as_float(s << 8), ex);
        }
        if ((m & 1) && lane == 0)
            stage[wslot][m] = make_float2(stage[wslot][0].x, 0.f);
        __syncwarp();

        int mp = (m + 1) & ~1;
        int k = 0;
        for (; k + 8 <= mp; k += 8) {
            float2 p0 = stage[wslot][k + 0 + h];
            float2 p1 = stage[wslot][k + 2 + h];
            float2 p2 = stage[wslot][k + 4 + h];
            float2 p3 = stage[wslot][k + 6 + h];
            uint4 v0 = *(const uint4*)(hbase + (unsigned)__float_as_int(p0.x));
            uint4 v1 = *(const uint4*)(hbase + (unsigned)__float_as_int(p1.x));
            uint4 v2 = *(const uint4*)(hbase + (unsigned)__float_as_int(p2.x));
            uint4 v3 = *(const uint4*)(hbase + (unsigned)__float_as_int(p3.x));
#define EDGE_STEP(vv, ww) do { \
                unsigned long long w_ = dup2(ww); \
                float2 a0_ = __half22float2(*(__half2*)&(vv).x); \
                float2 a1_ = __half22float2(*(__half2*)&(vv).y); \
                float2 a2_ = __half22float2(*(__half2*)&(vv).z); \
                float2 a3_ = __half22float2(*(__half2*)&(vv).w); \
                ffma2(acc0, w_, *(unsigned long long*)&a0_); \
                ffma2(acc1, w_, *(unsigned long long*)&a1_); \
                ffma2(acc2, w_, *(unsigned long long*)&a2_); \
                ffma2(acc3, w_, *(unsigned long long*)&a3_); \
            } while (0)
            EDGE_STEP(v0, p0.y);
            EDGE_STEP(v1, p1.y);
            EDGE_STEP(v2, p2.y);
            EDGE_STEP(v3, p3.y);
        }
        for (; k < mp; k += 2) {
            float2 p = stage[wslot][k + h];
            uint4 v = *(const uint4*)(hbase + (unsigned)__float_as_int(p.x));
            EDGE_STEP(v, p.y);
        }
#undef EDGE_STEP
        __syncwarp();
    }

#pragma unroll
    for (int o = 16; o; o >>= 1) denom += __shfl_xor_sync(0xffffffffu, denom, o);
    float inv = 1.f / denom;

    float2 f0 = *(float2*)&acc0;
    float2 f1 = *(float2*)&acc1;
    float2 f2 = *(float2*)&acc2;
    float2 f3 = *(float2*)&acc3;
    f0.x += __shfl_xor_sync(0xffffffffu, f0.x, 16);
    f0.y += __shfl_xor_sync(0xffffffffu, f0.y, 16);
    f1.x += __shfl_xor_sync(0xffffffffu, f1.x, 16);
    f1.y += __shfl_xor_sync(0xffffffffu, f1.y, 16);
    f2.x += __shfl_xor_sync(0xffffffffu, f2.x, 16);
    f2.y += __shfl_xor_sync(0xffffffffu, f2.y, 16);
    f3.x += __shfl_xor_sync(0xffffffffu, f3.x, 16);
    f3.y += __shfl_xor_sync(0xffffffffu, f3.y, 16);

    if (h == 0) {
        int fb = lane8 * 8;
        float4 b0 = *(const float4*)&bias[fb];
        float4 b1 = *(const float4*)&bias[fb + 4];
        float4 o0, o1;
        o0.x = f0.x * inv + b0.x;
        o0.y = f0.y * inv + b0.y;
        o0.z = f1.x * inv + b0.z;
        o0.w = f1.y * inv + b0.w;
        o1.x = f2.x * inv + b1.x;
        o1.y = f2.y * inv + b1.y;
        o1.z = f3.x * inv + b1.z;
        o1.w = f3.y * inv + b1.w;
        if (do_relu) {
            o0.x = fmaxf(o0.x, 0.f); o0.y = fmaxf(o0.y, 0.f);
            o0.z = fmaxf(o0.z, 0.f); o0.w = fmaxf(o0.w, 0.f);
            o1.x = fmaxf(o1.x, 0.f); o1.y = fmaxf(o1.y, 0.f);
            o1.z = fmaxf(o1.z, 0.f); o1.w = fmaxf(o1.w, 0.f);
        }
        *(float4*)&out[(size_t)node * D + fb] = o0;
        *(float4*)&out[(size_t)node * D + fb + 4] = o1;
    }
}

// ---------------------------------------------------------------- launch
extern "C" void kernel_launch(void* const* d_in, const int* in_sizes, int n_in,
                              void* d_out, int out_size) {
    const float* node_x = (const float*)d_in[0];
    const int*   ei     = (const int*)d_in[1];
    const float* W1     = (const float*)d_in[2];
    const float* as1    = (const float*)d_in[3];
    const float* ad1    = (const float*)d_in[4];
    const float* b1     = (const float*)d_in[5];
    const float* W2     = (const float*)d_in[6];
    const float* as2    = (const float*)d_in[7];
    const float* ad2    = (const float*)d_in[8];
    const float* b2     = (const float*)d_in[9];
    const float* Wout   = (const float*)d_in[10];
    const float* bout   = (const float*)d_in[11];
    float* out = (float*)d_out;

    int n = in_sizes[0] / D;       // 50000
    int E = in_sizes[1] / 2;       // 1600000

    float* x_ptr;
    __half *hh_ptr, *w16a_ptr, *w16b_ptr, *w16o_ptr;
    cudaGetSymbolAddress((void**)&x_ptr, g_x);
    cudaGetSymbolAddress((void**)&hh_ptr, g_hh);
    cudaGetSymbolAddress((void**)&w16a_ptr, g_w16a);
    cudaGetSymbolAddress((void**)&w16b_ptr, g_w16b);
    cudaGetSymbolAddress((void**)&w16o_ptr, g_w16o);

    const int SMEM_HMMA = (128 * XPAD + 128 * XPAD) * (int)sizeof(__half); // ~68 KB
    const int SMEM_OUT  = (64 * XPAD + 128 * WPAD) * (int)sizeof(__half);  // ~35 KB
    cudaFuncSetAttribute(hmma_gemm_place_kernel, cudaFuncAttributeMaxDynamicSharedMemorySize, SMEM_HMMA);
    cudaFuncSetAttribute(hmma_gemm_kernel, cudaFuncAttributeMaxDynamicSharedMemorySize, SMEM_HMMA);
    cudaFuncSetAttribute(hmma_out_kernel, cudaFuncAttributeMaxDynamicSharedMemorySize, SMEM_OUT);

    int tot = E + n;
    int nb = (n + SCAN_B - 1) / SCAN_B;
    int RB = (tot + 1023) / 1024;
    int agg_grid = (n * 32 + 255) / 256;
    int hmma_grid = (n + 127) / 128;
    int out_grid = (n + 63) / 64;
    int place_blocks = (tot + 256 * PLACE_EPT - 1) / (256 * PLACE_EPT);

    // CSR rank + W conversion + scan, one launch
    rank_scan_kernel<<<CONV_BLOCKS + RB + nb, 256>>>(ei, E, n, W1, W2, Wout, RB, nb, tot);

    // layer-1 GEMM + placement merged
    hmma_gemm_place_kernel<<<hmma_grid + place_blocks, 256, SMEM_HMMA>>>(
        node_x, w16a_ptr, hh_ptr, as1, ad1, n, ei, E, hmma_grid);
    gat_edge_kernel<<<agg_grid, 256>>>(hh_ptr, b1, x_ptr, n, 1);

    // layer 2
    hmma_gemm_kernel<<<hmma_grid, 256, SMEM_HMMA>>>(x_ptr, w16b_ptr, hh_ptr, as2, ad2, n);
    gat_edge_kernel<<<agg_grid, 256>>>(hh_ptr, b2, x_ptr, n, 0);

    // output linear (HMMA) + counter reset for next replay
    hmma_out_kernel<<<out_grid, 128, SMEM_OUT>>>(x_ptr, w16o_ptr, bout, out, n);
}